// round 5
// baseline (speedup 1.0000x reference)
#include <cuda_runtime.h>
#include <math.h>
#include <stdint.h>

#define NN 50000
#define EE 800000
#define HH 128
#define LL 3
#define NT 256
#define EPSBN 1e-5f

// ---------------- scratch ---------------------------------------------------
__device__ float g_h[NN * HH];
__device__ float g_p[NN * HH];
__device__ float g_agg[NN * HH];
__device__ float g_u[NN * HH];
__device__ float g_r[NN * HH];
__device__ int   g_cnt[NN];
__device__ float g_sum[LL * HH];
__device__ float g_sq[LL * HH];

// ---------------- tf32 / mma helpers ----------------------------------------
__device__ __forceinline__ unsigned f2tf32(float f) {
    unsigned u;
    asm("cvt.rna.tf32.f32 %0, %1;" : "=r"(u) : "f"(f));
    return u;
}
__device__ __forceinline__ void mma8(float acc[4], const uint4& a,
                                     unsigned b0, unsigned b1) {
    asm volatile(
        "mma.sync.aligned.m16n8k8.row.col.f32.tf32.tf32.f32 "
        "{%0,%1,%2,%3},{%4,%5,%6,%7},{%8,%9},{%0,%1,%2,%3};\n"
        : "+f"(acc[0]), "+f"(acc[1]), "+f"(acc[2]), "+f"(acc[3])
        : "r"(a.x), "r"(a.y), "r"(a.z), "r"(a.w), "r"(b0), "r"(b1));
}
// ldmatrix x4 (b16 view) == tf32 m16n8k8 A fragment from row-major smem
__device__ __forceinline__ uint4 ldsm4(unsigned addr) {
    uint4 r;
    asm volatile("ldmatrix.sync.aligned.m8n8.x4.shared.b16 {%0,%1,%2,%3}, [%4];"
        : "=r"(r.x), "=r"(r.y), "=r"(r.z), "=r"(r.w) : "r"(addr));
    return r;
}
// per-lane row address: lanes 0-15 -> rows 0..15 (col 8ks), lanes 16-31 -> rows, col +4
__device__ __forceinline__ unsigned a_lane_addr(const float* As, int lda,
                                                int q, int lane) {
    return (unsigned)__cvta_generic_to_shared(As)
         + ((((q * 16 + (lane & 15)) * lda) + 4 * (lane >> 4)) << 2);
}

// Stage KxN(128) row-major fp32 weight into tf32 B-fragment order.
__device__ __forceinline__ void stage_w_frag(float* Wf, const float* __restrict__ Wg,
                                             int KS, int tid)
{
    const int total = 2 * KS * 4 * 132;
    for (int i = tid; i < total; i += NT) {
        int grp = i / 132, off = i % 132;
        if (off < 128) {
            int s = off & 3, t = off >> 2;
            int gg = t >> 2, tt = t & 3;
            int hh = grp / (KS * 4);
            int rem = grp - hh * (KS * 4);
            int ks = rem >> 2, p = rem & 3;
            int k = 8 * ks + tt + ((s & 1) ? 4 : 0);
            int n = hh * 64 + 16 * p + gg + ((s >= 2) ? 8 : 0);
            Wf[i] = __uint_as_float(f2tf32(Wg[(size_t)k * 128 + n]));
        }
    }
}

// ---------------- streamed-W fp32 GEMM core (k_input / k_final) -------------
template<int RPT>
__device__ __forceinline__ void gemm_acc(const float* As, int lda, float* Ws,
                                         const float* __restrict__ Wg, int K,
                                         float acc[RPT][8], int tid)
{
    const int ty = tid >> 4, tx = tid & 15;
    for (int kc = 0; kc < K; kc += 16) {
        __syncthreads();
        for (int t = tid; t < 512; t += NT) {
            int kk = t >> 5, j4 = (t & 31) << 2;
            *(float4*)(Ws + kk * HH + j4) =
                *(const float4*)(Wg + (size_t)(kc + kk) * HH + j4);
        }
        __syncthreads();
        #pragma unroll
        for (int k = 0; k < 16; ++k) {
            float a[RPT];
            #pragma unroll
            for (int i = 0; i < RPT; ++i) a[i] = As[(ty * RPT + i) * lda + kc + k];
            float4 b0 = *(const float4*)(Ws + k * HH + tx * 8);
            float4 b1 = *(const float4*)(Ws + k * HH + tx * 8 + 4);
            float bb[8] = {b0.x, b0.y, b0.z, b0.w, b1.x, b1.y, b1.z, b1.w};
            #pragma unroll
            for (int i = 0; i < RPT; ++i)
                #pragma unroll
                for (int j = 0; j < 8; ++j)
                    acc[i][j] = fmaf(a[i], bb[j], acc[i][j]);
        }
    }
    __syncthreads();
}

// ---------------- zero init --------------------------------------------------
__global__ void k_zero(int n)
{
    int total = n * HH;
    for (int i = blockIdx.x * blockDim.x + threadIdx.x; i < total;
         i += gridDim.x * blockDim.x) {
        g_agg[i] = 0.f;
        if (i < n) g_cnt[i] = 0;
        if (i < LL * HH) { g_sum[i] = 0.f; g_sq[i] = 0.f; }
    }
}

// ---------------- input MLP + degree count -----------------------------------
__global__ __launch_bounds__(NT) void k_input(
    const float* __restrict__ x,
    const float* __restrict__ W0, const float* __restrict__ b0,
    const float* __restrict__ W1, const float* __restrict__ b1,
    const int* __restrict__ dst, int E, int n)
{
    extern __shared__ float smem[];
    float* As  = smem;
    float* Ws  = As + 64 * 132;
    float* w0s = Ws + 2048;
    float* b0s = w0s + 256;
    float* xs  = b0s + 128;
    const int tid = threadIdx.x;
    const int base = blockIdx.x * 64;

    for (int e = blockIdx.x * blockDim.x + tid; e < E; e += gridDim.x * blockDim.x)
        atomicAdd(&g_cnt[dst[e]], 1);

    for (int t = tid; t < 256; t += NT) w0s[t] = W0[t];
    for (int t = tid; t < 128; t += NT) b0s[t] = b0[t];
    if (tid < 128) {
        int row = tid >> 1;
        xs[tid] = (base + row < n) ? x[(size_t)(base + row) * 2 + (tid & 1)] : 0.f;
    }
    __syncthreads();

    for (int t = tid; t < 64 * 32; t += NT) {
        int row = t >> 5, j = (t & 31) << 2;
        float x0 = xs[row * 2], x1 = xs[row * 2 + 1];
        float4 v;
        v.x = fmaxf(fmaf(x0, w0s[j + 0], fmaf(x1, w0s[128 + j + 0], b0s[j + 0])), 0.f);
        v.y = fmaxf(fmaf(x0, w0s[j + 1], fmaf(x1, w0s[128 + j + 1], b0s[j + 1])), 0.f);
        v.z = fmaxf(fmaf(x0, w0s[j + 2], fmaf(x1, w0s[128 + j + 2], b0s[j + 2])), 0.f);
        v.w = fmaxf(fmaf(x0, w0s[j + 3], fmaf(x1, w0s[128 + j + 3], b0s[j + 3])), 0.f);
        *(float4*)(As + row * 132 + j) = v;
    }

    float acc[4][8] = {};
    gemm_acc<4>(As, 132, Ws, W1, HH, acc, tid);

    const int ty = tid >> 4, tx = tid & 15, c0 = tx * 8;
    #pragma unroll
    for (int i = 0; i < 4; ++i) {
        int row = base + ty * 4 + i;
        if (row < n) {
            #pragma unroll
            for (int j = 0; j < 8; ++j)
                g_h[(size_t)row * HH + c0 + j] = fmaxf(acc[i][j] + b1[c0 + j], 0.f);
        }
    }
}

// ---------------- P = BN?(h) @ W1a_top : ldsm + fused BN ---------------------
__global__ void __launch_bounds__(NT, 2) k_precompute(
    const float* __restrict__ W,
    const float* __restrict__ gamma, const float* __restrict__ beta,
    int bnl, int n, int ntiles)
{
    extern __shared__ float smem[];
    float* Wf = smem;               // 128*132
    float* As = Wf + 128 * 132;     // 64*132 row-major
    float* sc = As + 64 * 132;      // 128
    float* sh = sc + 128;           // 128
    const int tid  = threadIdx.x;
    const int lane = tid & 31, w = tid >> 5;
    const int q = w & 3, h = w >> 2;
    const int g = lane >> 2, tg = lane & 3;

    stage_w_frag(Wf, W, 16, tid);
    if (tid < 128) {
        if (bnl >= 0) {
            float invn = 1.f / (float)n;
            float mu  = g_sum[bnl * HH + tid] * invn;
            float var = g_sq[bnl * HH + tid] * invn - mu * mu;
            float s = gamma[tid] * rsqrtf(var + EPSBN);
            sc[tid] = s; sh[tid] = beta[tid] - mu * s;
        } else { sc[tid] = 1.f; sh[tid] = 0.f; }
    }
    const unsigned alane = a_lane_addr(As, 132, q, lane);

    for (int tile = blockIdx.x; tile < ntiles; tile += gridDim.x) {
        const int base = tile * 64;
        __syncthreads();
        for (int wi = tid; wi < 2048; wi += NT) {
            int row = wi >> 5, j = (wi & 31) << 2;
            int node = base + row;
            float4 v = make_float4(0.f, 0.f, 0.f, 0.f);
            if (node < n) {
                if (bnl >= 0) {
                    v = *(const float4*)(g_r + (size_t)node * HH + j);
                    v.x = v.x * sc[j + 0] + sh[j + 0];
                    v.y = v.y * sc[j + 1] + sh[j + 1];
                    v.z = v.z * sc[j + 2] + sh[j + 2];
                    v.w = v.w * sc[j + 3] + sh[j + 3];
                    *(float4*)(g_h + (size_t)node * HH + j) = v;
                } else {
                    v = *(const float4*)(g_h + (size_t)node * HH + j);
                }
            }
            uint4 st = make_uint4(f2tf32(v.x), f2tf32(v.y), f2tf32(v.z), f2tf32(v.w));
            *(uint4*)(As + row * 132 + j) = st;
        }
        __syncthreads();

        float acc[8][4] = {};
        #pragma unroll
        for (int ks = 0; ks < 16; ++ks) {
            uint4 a = ldsm4(alane + (ks << 5));
            #pragma unroll
            for (int p = 0; p < 4; ++p) {
                uint4 b = *(const uint4*)(Wf + ((h * 16 + ks) * 4 + p) * 132 + lane * 4);
                mma8(acc[2 * p],     a, b.x, b.y);
                mma8(acc[2 * p + 1], a, b.z, b.w);
            }
        }
        int r0 = base + q * 16 + g;
        #pragma unroll
        for (int nt = 0; nt < 8; ++nt) {
            int col = h * 64 + 8 * nt + 2 * tg;
            if (r0 < n)
                *(float2*)(g_p + (size_t)r0 * HH + col) = make_float2(acc[nt][0], acc[nt][1]);
            if (r0 + 8 < n)
                *(float2*)(g_p + (size_t)(r0 + 8) * HH + col) = make_float2(acc[nt][2], acc[nt][3]);
        }
    }
}

// ---------------- edge kernel: ldsm producer + direct red scatter ------------
__global__ void __launch_bounds__(NT, 2) k_edge(
    const float* __restrict__ ea,
    const int* __restrict__ src, const int* __restrict__ dst,
    const float* __restrict__ Wtail,
    const float* __restrict__ b1a,
    const float* __restrict__ W1b, const float* __restrict__ b1b,
    int E, int ntiles)
{
    extern __shared__ float smem[];
    float* Wf  = smem;                 // 128*132
    float* As  = Wf + 128 * 132;       // 64*132 row-major messages
    float* wt  = As + 64 * 132;        // 2*128
    float* bs  = wt + 256;             // b1a
    float* eas = bs + 128;             // 2*64
    int*   sd  = (int*)(eas + 128);    // src 64 | dst 64

    const int tid  = threadIdx.x;
    const int lane = tid & 31, w = tid >> 5;
    const int q = w & 3, h = w >> 2;
    const int g = lane >> 2, tg = lane & 3;

    stage_w_frag(Wf, W1b, 16, tid);
    for (int t = tid; t < 256; t += NT) wt[t] = Wtail[t];
    if (tid < 128) bs[tid] = b1a[tid];

    float bv[16];
    #pragma unroll
    for (int nt = 0; nt < 8; ++nt) {
        int col = h * 64 + 8 * nt + 2 * tg;
        bv[2 * nt]     = b1b[col];
        bv[2 * nt + 1] = b1b[col + 1];
    }
    const unsigned alane = a_lane_addr(As, 132, q, lane);

    for (int tile = blockIdx.x; tile < ntiles; tile += gridDim.x) {
        const int e0 = tile * 64;
        __syncthreads();
        if (tid < 64) {
            int e = e0 + tid;
            if (e < E) {
                sd[tid]      = src[e];
                sd[64 + tid] = dst[e];
                eas[2 * tid]     = ea[(size_t)e * 2];
                eas[2 * tid + 1] = ea[(size_t)e * 2 + 1];
            } else {
                sd[tid] = 0; sd[64 + tid] = -1;
                eas[2 * tid] = 0.f; eas[2 * tid + 1] = 0.f;
            }
        }
        __syncthreads();

        // producer: gather + rank-2 + bias + ReLU -> row-major tf32 tile
        for (int wi = tid; wi < 2048; wi += NT) {
            int row = wi >> 5, j = (wi & 31) << 2;
            const float4 p = *(const float4*)(g_p + (size_t)sd[row] * HH + j);
            float ev0 = eas[2 * row], ev1 = eas[2 * row + 1];
            float m0 = fmaf(ev0, wt[j + 0], fmaf(ev1, wt[128 + j + 0], p.x + bs[j + 0]));
            float m1 = fmaf(ev0, wt[j + 1], fmaf(ev1, wt[128 + j + 1], p.y + bs[j + 1]));
            float m2 = fmaf(ev0, wt[j + 2], fmaf(ev1, wt[128 + j + 2], p.z + bs[j + 2]));
            float m3 = fmaf(ev0, wt[j + 3], fmaf(ev1, wt[128 + j + 3], p.w + bs[j + 3]));
            uint4 st = make_uint4(f2tf32(fmaxf(m0, 0.f)), f2tf32(fmaxf(m1, 0.f)),
                                  f2tf32(fmaxf(m2, 0.f)), f2tf32(fmaxf(m3, 0.f)));
            *(uint4*)(As + row * 132 + j) = st;
        }
        __syncthreads();

        float acc[8][4] = {};
        #pragma unroll
        for (int ks = 0; ks < 16; ++ks) {
            uint4 a = ldsm4(alane + (ks << 5));
            #pragma unroll
            for (int p = 0; p < 4; ++p) {
                uint4 b = *(const uint4*)(Wf + ((h * 16 + ks) * 4 + p) * 132 + lane * 4);
                mma8(acc[2 * p],     a, b.x, b.y);
                mma8(acc[2 * p + 1], a, b.z, b.w);
            }
        }

        // direct bias + ReLU + red.v2 scatter from accumulators
        int d0 = sd[64 + q * 16 + g];
        int d1 = sd[64 + q * 16 + g + 8];
        #pragma unroll
        for (int nt = 0; nt < 8; ++nt) {
            int col = h * 64 + 8 * nt + 2 * tg;
            if (d0 >= 0) {
                float v0 = fmaxf(acc[nt][0] + bv[2 * nt],     0.f);
                float v1 = fmaxf(acc[nt][1] + bv[2 * nt + 1], 0.f);
                asm volatile("red.global.add.v2.f32 [%0], {%1,%2};"
                             :: "l"(g_agg + (size_t)d0 * HH + col), "f"(v0), "f"(v1)
                             : "memory");
            }
            if (d1 >= 0) {
                float v2 = fmaxf(acc[nt][2] + bv[2 * nt],     0.f);
                float v3 = fmaxf(acc[nt][3] + bv[2 * nt + 1], 0.f);
                asm volatile("red.global.add.v2.f32 [%0], {%1,%2};"
                             :: "l"(g_agg + (size_t)d1 * HH + col), "f"(v2), "f"(v3)
                             : "memory");
            }
        }
    }
}

// ---------------- update1: U = relu([h | agg/deg] @ W2a + b2a) ---------------
__global__ void __launch_bounds__(NT, 1) k_update1(
    const float* __restrict__ W2a, const float* __restrict__ b2a,
    int n, int ntiles, int zero_agg)
{
    extern __shared__ float smem[];
    float* Wf   = smem;                // 256*132
    float* As   = Wf + 256 * 132;      // 64*260 row-major (K=256)
    float* sinv = As + 64 * 260;       // 64
    const int tid  = threadIdx.x;
    const int lane = tid & 31, w = tid >> 5;
    const int q = w & 3, h = w >> 2;
    const int g = lane >> 2, tg = lane & 3;

    stage_w_frag(Wf, W2a, 32, tid);
    float bv[16];
    #pragma unroll
    for (int nt = 0; nt < 8; ++nt) {
        int col = h * 64 + 8 * nt + 2 * tg;
        bv[2 * nt]     = b2a[col];
        bv[2 * nt + 1] = b2a[col + 1];
    }
    const unsigned alane = a_lane_addr(As, 260, q, lane);

    for (int tile = blockIdx.x; tile < ntiles; tile += gridDim.x) {
        const int base = tile * 64;
        __syncthreads();
        if (tid < 64) {
            int node = base + tid;
            sinv[tid] = (node < n) ? 1.f / fmaxf((float)g_cnt[node], 1.f) : 0.f;
        }
        __syncthreads();

        for (int wi = tid; wi < 4096; wi += NT) {
            int row = wi >> 6, j = (wi & 63) << 2;
            int node = base + row;
            float4 v = make_float4(0.f, 0.f, 0.f, 0.f);
            if (node < n) {
                if (j < 128) {
                    v = *(const float4*)(g_h + (size_t)node * HH + j);
                } else {
                    v = *(const float4*)(g_agg + (size_t)node * HH + (j - 128));
                    float iv = sinv[row];
                    v.x *= iv; v.y *= iv; v.z *= iv; v.w *= iv;
                    if (zero_agg)
                        *(float4*)(g_agg + (size_t)node * HH + (j - 128)) =
                            make_float4(0.f, 0.f, 0.f, 0.f);
                }
            }
            uint4 st = make_uint4(f2tf32(v.x), f2tf32(v.y), f2tf32(v.z), f2tf32(v.w));
            *(uint4*)(As + row * 260 + j) = st;
        }
        __syncthreads();

        float acc[8][4] = {};
        #pragma unroll
        for (int ks = 0; ks < 32; ++ks) {
            uint4 a = ldsm4(alane + (ks << 5));
            #pragma unroll
            for (int p = 0; p < 4; ++p) {
                uint4 b = *(const uint4*)(Wf + ((h * 32 + ks) * 4 + p) * 132 + lane * 4);
                mma8(acc[2 * p],     a, b.x, b.y);
                mma8(acc[2 * p + 1], a, b.z, b.w);
            }
        }

        int r0 = base + q * 16 + g;
        #pragma unroll
        for (int nt = 0; nt < 8; ++nt) {
            int col = h * 64 + 8 * nt + 2 * tg;
            if (r0 < n)
                *(float2*)(g_u + (size_t)r0 * HH + col) =
                    make_float2(fmaxf(acc[nt][0] + bv[2 * nt], 0.f),
                                fmaxf(acc[nt][1] + bv[2 * nt + 1], 0.f));
            if (r0 + 8 < n)
                *(float2*)(g_u + (size_t)(r0 + 8) * HH + col) =
                    make_float2(fmaxf(acc[nt][2] + bv[2 * nt], 0.f),
                                fmaxf(acc[nt][3] + bv[2 * nt + 1], 0.f));
        }
    }
}

// ---------------- update2: out=sigmoid(U@W2b+b), r=h+out, BN stats -----------
__global__ void __launch_bounds__(NT, 2) k_update2(
    const float* __restrict__ W2b, const float* __restrict__ b2b,
    int l, int n, int ntiles)
{
    extern __shared__ float smem[];
    float* Wf = smem;               // 128*132
    float* As = Wf + 128 * 132;     // 64*132 (A fragments, then r tile)
    const int tid  = threadIdx.x;
    const int lane = tid & 31, w = tid >> 5;
    const int q = w & 3, h = w >> 2;
    const int g = lane >> 2, tg = lane & 3;

    stage_w_frag(Wf, W2b, 16, tid);
    float bv[16];
    #pragma unroll
    for (int nt = 0; nt < 8; ++nt) {
        int col = h * 64 + 8 * nt + 2 * tg;
        bv[2 * nt]     = b2b[col];
        bv[2 * nt + 1] = b2b[col + 1];
    }
    const unsigned alane = a_lane_addr(As, 132, q, lane);

    for (int tile = blockIdx.x; tile < ntiles; tile += gridDim.x) {
        const int base = tile * 64;
        __syncthreads();
        for (int wi = tid; wi < 2048; wi += NT) {
            int row = wi >> 5, j = (wi & 31) << 2;
            float4 v = make_float4(0.f, 0.f, 0.f, 0.f);
            if (base + row < n)
                v = *(const float4*)(g_u + (size_t)(base + row) * HH + j);
            uint4 st = make_uint4(f2tf32(v.x), f2tf32(v.y), f2tf32(v.z), f2tf32(v.w));
            *(uint4*)(As + row * 132 + j) = st;
        }
        __syncthreads();

        float acc[8][4] = {};
        #pragma unroll
        for (int ks = 0; ks < 16; ++ks) {
            uint4 a = ldsm4(alane + (ks << 5));
            #pragma unroll
            for (int p = 0; p < 4; ++p) {
                uint4 b = *(const uint4*)(Wf + ((h * 16 + ks) * 4 + p) * 132 + lane * 4);
                mma8(acc[2 * p],     a, b.x, b.y);
                mma8(acc[2 * p + 1], a, b.z, b.w);
            }
        }
        __syncthreads();   // ldsm reads done -> reuse As as r tile

        int r0 = base + q * 16 + g;
        #pragma unroll
        for (int nt = 0; nt < 8; ++nt) {
            int col = h * 64 + 8 * nt + 2 * tg;
            float2 rv0 = make_float2(0.f, 0.f), rv1 = make_float2(0.f, 0.f);
            if (r0 < n) {
                float2 hv = *(const float2*)(g_h + (size_t)r0 * HH + col);
                rv0.x = hv.x + 1.f / (1.f + expf(-(acc[nt][0] + bv[2 * nt])));
                rv0.y = hv.y + 1.f / (1.f + expf(-(acc[nt][1] + bv[2 * nt + 1])));
            }
            if (r0 + 8 < n) {
                float2 hv = *(const float2*)(g_h + (size_t)(r0 + 8) * HH + col);
                rv1.x = hv.x + 1.f / (1.f + expf(-(acc[nt][2] + bv[2 * nt])));
                rv1.y = hv.y + 1.f / (1.f + expf(-(acc[nt][3] + bv[2 * nt + 1])));
            }
            *(float2*)(As + (q * 16 + g) * 132 + col)     = rv0;
            *(float2*)(As + (q * 16 + g + 8) * 132 + col) = rv1;
        }
        __syncthreads();

        for (int wi = tid; wi < 2048; wi += NT) {
            int row = wi >> 5, j = (wi & 31) << 2;
            if (base + row < n) {
                float4 v = *(const float4*)(As + row * 132 + j);
                *(float4*)(g_r + (size_t)(base + row) * HH + j) = v;
            }
        }
        {
            int c = tid & 127, half = tid >> 7;
            float s = 0.f, s2 = 0.f;
            #pragma unroll 8
            for (int r = half * 32; r < half * 32 + 32; ++r) {
                float v = As[r * 132 + c];
                s += v; s2 += v * v;
            }
            atomicAdd(&g_sum[l * HH + c], s);
            atomicAdd(&g_sq[l * HH + c],  s2);
        }
    }
}

// ---------------- final MLP with fused BN(layer 2) ----------------------------
__global__ __launch_bounds__(NT) void k_final(
    const float* __restrict__ Wf, const float* __restrict__ bf,
    const float* __restrict__ Wo, const float* __restrict__ bo,
    const float* __restrict__ gamma, const float* __restrict__ beta,
    int bnl, float* __restrict__ out, int n)
{
    extern __shared__ float smem[];
    float* As = smem;
    float* Ws = As + 64 * 132;
    float* sc = Ws + 2048;
    float* sh = sc + 128;
    const int tid = threadIdx.x;
    const int base = blockIdx.x * 64;

    if (tid < 128) {
        float invn = 1.f / (float)n;
        float mu  = g_sum[bnl * HH + tid] * invn;
        float var = g_sq[bnl * HH + tid] * invn - mu * mu;
        float s = gamma[tid] * rsqrtf(var + EPSBN);
        sc[tid] = s; sh[tid] = beta[tid] - mu * s;
    }
    __syncthreads();

    for (int t = tid; t < 64 * 32; t += NT) {
        int row = t >> 5, j = (t & 31) << 2;
        float4 v = make_float4(0.f, 0.f, 0.f, 0.f);
        if (base + row < n) {
            v = *(const float4*)(g_r + (size_t)(base + row) * HH + j);
            v.x = v.x * sc[j + 0] + sh[j + 0];
            v.y = v.y * sc[j + 1] + sh[j + 1];
            v.z = v.z * sc[j + 2] + sh[j + 2];
            v.w = v.w * sc[j + 3] + sh[j + 3];
        }
        *(float4*)(As + row * 132 + j) = v;
    }

    float acc[4][8] = {};
    gemm_acc<4>(As, 132, Ws, Wf, HH, acc, tid);

    const int ty = tid >> 4, tx = tid & 15, c0 = tx * 8;
    #pragma unroll
    for (int i = 0; i < 4; ++i)
        #pragma unroll
        for (int j = 0; j < 8; ++j)
            As[(ty * 4 + i) * 132 + c0 + j] = fmaxf(acc[i][j] + bf[c0 + j], 0.f);
    __syncthreads();

    const int w = tid >> 5, lane = tid & 31;
    #pragma unroll
    for (int rr = 0; rr < 8; ++rr) {
        int row = w * 8 + rr;
        float sAcc = 0.f;
        #pragma unroll
        for (int qq = 0; qq < 4; ++qq)
            sAcc += As[row * 132 + lane + 32 * qq] * Wo[lane + 32 * qq];
        #pragma unroll
        for (int off = 16; off; off >>= 1)
            sAcc += __shfl_xor_sync(0xffffffffu, sAcc, off);
        if (lane == 0 && base + row < n)
            out[base + row] = 1.f / (1.f + expf(-sAcc));
    }
}

// ---------------- launcher -----------------------------------------------------
extern "C" void kernel_launch(void* const* d_in, const int* in_sizes, int n_in,
                              void* d_out, int out_size)
{
    const float* x    = (const float*)d_in[0];
    const float* ea   = (const float*)d_in[1];
    const int*   ei   = (const int*)  d_in[2];
    const float* W0   = (const float*)d_in[4];
    const float* b0   = (const float*)d_in[5];
    const float* W1   = (const float*)d_in[6];
    const float* b1   = (const float*)d_in[7];
    const float* W1a  = (const float*)d_in[8];
    const float* b1a  = (const float*)d_in[9];
    const float* W1b  = (const float*)d_in[10];
    const float* b1b  = (const float*)d_in[11];
    const float* W2a  = (const float*)d_in[12];
    const float* b2a  = (const float*)d_in[13];
    const float* W2b  = (const float*)d_in[14];
    const float* b2b  = (const float*)d_in[15];
    const float* gam  = (const float*)d_in[16];
    const float* bet  = (const float*)d_in[17];
    const float* Wf   = (const float*)d_in[18];
    const float* bf   = (const float*)d_in[19];
    const float* Wo   = (const float*)d_in[20];
    const float* bo   = (const float*)d_in[21];
    float* out = (float*)d_out;

    const int n = in_sizes[0] / 2;
    const int E = in_sizes[2] / 2;
    const int* srcp = ei;
    const int* dstp = ei + E;

    const int nb_n     = (n + 63) / 64;
    const int ntiles_n = nb_n;
    const int ntiles_e = (E + 63) / 64;
    const int gPers    = 296;
    const int gPers1   = 148;

    const size_t SM_IN = (size_t)(64 * 132 + 2048 + 256 + 128 + 128) * 4;
    const size_t SM_P  = (size_t)(128 * 132 + 64 * 132 + 256) * 4;             // 102400
    const size_t SM_E  = (size_t)(128 * 132 + 64 * 132 + 256 + 128 + 128) * 4
                         + 128 * 4;                                             // 103936
    const size_t SM_U1 = (size_t)(256 * 132 + 64 * 260 + 64) * 4;              // 201984
    const size_t SM_U2 = (size_t)(128 * 132 + 64 * 132) * 4;                   // 101376
    const size_t SM_F  = (size_t)(64 * 132 + 2048 + 256) * 4;

    cudaFuncSetAttribute(k_edge, cudaFuncAttributeMaxDynamicSharedMemorySize, (int)SM_E);
    cudaFuncSetAttribute(k_precompute, cudaFuncAttributeMaxDynamicSharedMemorySize, (int)SM_P);
    cudaFuncSetAttribute(k_update1, cudaFuncAttributeMaxDynamicSharedMemorySize, (int)SM_U1);
    cudaFuncSetAttribute(k_update2, cudaFuncAttributeMaxDynamicSharedMemorySize, (int)SM_U2);

    k_zero<<<1024, 256>>>(n);
    k_input<<<nb_n, NT, SM_IN>>>(x, W0, b0, W1, b1, dstp, E, n);

    for (int l = 0; l < LL; ++l) {
        const float* W1a_l  = W1a + (size_t)l * 130 * 128;
        const float* W1a_t  = W1a_l + 128 * 128;
        const float* b1a_l  = b1a + (size_t)l * 128;
        const float* W1b_l  = W1b + (size_t)l * 128 * 128;
        const float* b1b_l  = b1b + (size_t)l * 128;
        const float* W2a_l  = W2a + (size_t)l * 256 * 128;
        const float* b2a_l  = b2a + (size_t)l * 128;
        const float* W2b_l  = W2b + (size_t)l * 128 * 128;
        const float* b2b_l  = b2b + (size_t)l * 128;
        // BN params of the PREVIOUS layer feed k_precompute
        const float* gam_p  = (l > 0) ? gam + (size_t)(l - 1) * 128 : gam;
        const float* bet_p  = (l > 0) ? bet + (size_t)(l - 1) * 128 : bet;

        k_precompute<<<gPers, NT, SM_P>>>(W1a_l, gam_p, bet_p, l - 1, n, ntiles_n);
        k_edge<<<gPers, NT, SM_E>>>(ea, srcp, dstp, W1a_t, b1a_l, W1b_l, b1b_l,
                                    E, ntiles_e);
        k_update1<<<gPers1, NT, SM_U1>>>(W2a_l, b2a_l, n, ntiles_n,
                                         (l < LL - 1) ? 1 : 0);
        k_update2<<<gPers, NT, SM_U2>>>(W2b_l, b2b_l, l, n, ntiles_n);
    }

    k_final<<<nb_n, NT, SM_F>>>(Wf, bf, Wo, bo,
                                gam + (size_t)(LL - 1) * 128,
                                bet + (size_t)(LL - 1) * 128,
                                LL - 1, out, n);
}

// round 6
// speedup vs baseline: 1.2155x; 1.2155x over previous
#include <cuda_runtime.h>
#include <cuda_bf16.h>
#include <math.h>
#include <stdint.h>

#define NN 50000
#define EE 800000
#define HH 128
#define LL 3
#define NT 256
#define EPSBN 1e-5f

// ---------------- scratch ---------------------------------------------------
__device__ float    g_h[NN * HH];
__device__ unsigned g_pb[NN * 64];     // P in bf16x2 (64 uints per row)
__device__ float    g_agg[NN * HH];
__device__ float    g_u[NN * HH];
__device__ float    g_r[NN * HH];
__device__ int      g_cnt[NN];
__device__ float    g_sum[LL * HH];
__device__ float    g_sq[LL * HH];

// ---------------- mma / ldmatrix helpers -------------------------------------
__device__ __forceinline__ unsigned f2tf32(float f) {
    unsigned u;
    asm("cvt.rna.tf32.f32 %0, %1;" : "=r"(u) : "f"(f));
    return u;
}
__device__ __forceinline__ void mma8(float acc[4], const uint4& a,
                                     unsigned b0, unsigned b1) {
    asm volatile(
        "mma.sync.aligned.m16n8k8.row.col.f32.tf32.tf32.f32 "
        "{%0,%1,%2,%3},{%4,%5,%6,%7},{%8,%9},{%0,%1,%2,%3};\n"
        : "+f"(acc[0]), "+f"(acc[1]), "+f"(acc[2]), "+f"(acc[3])
        : "r"(a.x), "r"(a.y), "r"(a.z), "r"(a.w), "r"(b0), "r"(b1));
}
__device__ __forceinline__ void mma16(float acc[4], const uint4& a,
                                      unsigned b0, unsigned b1) {
    asm volatile(
        "mma.sync.aligned.m16n8k16.row.col.f32.bf16.bf16.f32 "
        "{%0,%1,%2,%3},{%4,%5,%6,%7},{%8,%9},{%0,%1,%2,%3};\n"
        : "+f"(acc[0]), "+f"(acc[1]), "+f"(acc[2]), "+f"(acc[3])
        : "r"(a.x), "r"(a.y), "r"(a.z), "r"(a.w), "r"(b0), "r"(b1));
}
__device__ __forceinline__ uint4 ldsm4(unsigned addr) {
    uint4 r;
    asm volatile("ldmatrix.sync.aligned.m8n8.x4.shared.b16 {%0,%1,%2,%3}, [%4];"
        : "=r"(r.x), "=r"(r.y), "=r"(r.z), "=r"(r.w) : "r"(addr));
    return r;
}
// tf32 A-frag lane address (fp32 row-major, lda floats)
__device__ __forceinline__ unsigned a_lane_addr(const float* As, int lda,
                                                int q, int lane) {
    return (unsigned)__cvta_generic_to_shared(As)
         + ((((q * 16 + (lane & 15)) * lda) + 4 * (lane >> 4)) << 2);
}
// bf16 A-frag lane address (bf16 row-major, 136 bf16 = 272B rows)
__device__ __forceinline__ unsigned a_lane_addr_bf(const __nv_bfloat16* As,
                                                   int q, int lane) {
    return (unsigned)__cvta_generic_to_shared(As)
         + (q * 16 + (lane & 7) + 8 * ((lane >> 3) & 1)) * 272
         + (lane >> 4) * 16;
}

// Stage KxN(128) row-major fp32 weight into tf32 B-fragment order (k8 steps).
__device__ __forceinline__ void stage_w_frag(float* Wf, const float* __restrict__ Wg,
                                             int KS, int tid)
{
    const int total = 2 * KS * 4 * 132;
    for (int i = tid; i < total; i += NT) {
        int grp = i / 132, off = i % 132;
        if (off < 128) {
            int s = off & 3, t = off >> 2;
            int gg = t >> 2, tt = t & 3;
            int hh = grp / (KS * 4);
            int rem = grp - hh * (KS * 4);
            int ks = rem >> 2, p = rem & 3;
            int k = 8 * ks + tt + ((s & 1) ? 4 : 0);
            int n = hh * 64 + 16 * p + gg + ((s >= 2) ? 8 : 0);
            Wf[i] = __uint_as_float(f2tf32(Wg[(size_t)k * 128 + n]));
        }
    }
}

// Stage KxN(128) row-major fp32 weight into bf16 B-fragment order (k16 steps).
// group grp = hh*(KS*4) + ks*4 + pp ; element = lane*4 + s ; pad to 132.
__device__ __forceinline__ void stage_w_bf16(unsigned* Wf, const float* __restrict__ Wg,
                                             int KS, int tid)
{
    const int total = 2 * KS * 4 * 132;
    for (int i = tid; i < total; i += NT) {
        int grp = i / 132, off = i % 132;
        if (off < 128) {
            int s = off & 3, lane = off >> 2;
            int g = lane >> 2, t = lane & 3;
            int hh = grp / (KS * 4);
            int rem = grp - hh * (KS * 4);
            int ks = rem >> 2, pp = rem & 3;
            int p = 2 * pp + (s >> 1);
            int bsel = s & 1;
            int n = hh * 64 + p * 8 + g;
            int k0 = ks * 16 + 2 * t + 8 * bsel;
            __nv_bfloat162 v = __floats2bfloat162_rn(Wg[(size_t)k0 * 128 + n],
                                                     Wg[(size_t)(k0 + 1) * 128 + n]);
            Wf[i] = *(unsigned*)&v;
        }
    }
}

// ---------------- streamed-W fp32 GEMM core (k_input / k_final) -------------
template<int RPT>
__device__ __forceinline__ void gemm_acc(const float* As, int lda, float* Ws,
                                         const float* __restrict__ Wg, int K,
                                         float acc[RPT][8], int tid)
{
    const int ty = tid >> 4, tx = tid & 15;
    for (int kc = 0; kc < K; kc += 16) {
        __syncthreads();
        for (int t = tid; t < 512; t += NT) {
            int kk = t >> 5, j4 = (t & 31) << 2;
            *(float4*)(Ws + kk * HH + j4) =
                *(const float4*)(Wg + (size_t)(kc + kk) * HH + j4);
        }
        __syncthreads();
        #pragma unroll
        for (int k = 0; k < 16; ++k) {
            float a[RPT];
            #pragma unroll
            for (int i = 0; i < RPT; ++i) a[i] = As[(ty * RPT + i) * lda + kc + k];
            float4 b0 = *(const float4*)(Ws + k * HH + tx * 8);
            float4 b1 = *(const float4*)(Ws + k * HH + tx * 8 + 4);
            float bb[8] = {b0.x, b0.y, b0.z, b0.w, b1.x, b1.y, b1.z, b1.w};
            #pragma unroll
            for (int i = 0; i < RPT; ++i)
                #pragma unroll
                for (int j = 0; j < 8; ++j)
                    acc[i][j] = fmaf(a[i], bb[j], acc[i][j]);
        }
    }
    __syncthreads();
}

// ---------------- zero init --------------------------------------------------
__global__ void k_zero(int n)
{
    int total = n * HH;
    for (int i = blockIdx.x * blockDim.x + threadIdx.x; i < total;
         i += gridDim.x * blockDim.x) {
        g_agg[i] = 0.f;
        if (i < n) g_cnt[i] = 0;
        if (i < LL * HH) { g_sum[i] = 0.f; g_sq[i] = 0.f; }
    }
}

// ---------------- input MLP + degree count -----------------------------------
__global__ __launch_bounds__(NT) void k_input(
    const float* __restrict__ x,
    const float* __restrict__ W0, const float* __restrict__ b0,
    const float* __restrict__ W1, const float* __restrict__ b1,
    const int* __restrict__ dst, int E, int n)
{
    extern __shared__ float smem[];
    float* As  = smem;
    float* Ws  = As + 64 * 132;
    float* w0s = Ws + 2048;
    float* b0s = w0s + 256;
    float* xs  = b0s + 128;
    const int tid = threadIdx.x;
    const int base = blockIdx.x * 64;

    for (int e = blockIdx.x * blockDim.x + tid; e < E; e += gridDim.x * blockDim.x)
        atomicAdd(&g_cnt[dst[e]], 1);

    for (int t = tid; t < 256; t += NT) w0s[t] = W0[t];
    for (int t = tid; t < 128; t += NT) b0s[t] = b0[t];
    if (tid < 128) {
        int row = tid >> 1;
        xs[tid] = (base + row < n) ? x[(size_t)(base + row) * 2 + (tid & 1)] : 0.f;
    }
    __syncthreads();

    for (int t = tid; t < 64 * 32; t += NT) {
        int row = t >> 5, j = (t & 31) << 2;
        float x0 = xs[row * 2], x1 = xs[row * 2 + 1];
        float4 v;
        v.x = fmaxf(fmaf(x0, w0s[j + 0], fmaf(x1, w0s[128 + j + 0], b0s[j + 0])), 0.f);
        v.y = fmaxf(fmaf(x0, w0s[j + 1], fmaf(x1, w0s[128 + j + 1], b0s[j + 1])), 0.f);
        v.z = fmaxf(fmaf(x0, w0s[j + 2], fmaf(x1, w0s[128 + j + 2], b0s[j + 2])), 0.f);
        v.w = fmaxf(fmaf(x0, w0s[j + 3], fmaf(x1, w0s[128 + j + 3], b0s[j + 3])), 0.f);
        *(float4*)(As + row * 132 + j) = v;
    }

    float acc[4][8] = {};
    gemm_acc<4>(As, 132, Ws, W1, HH, acc, tid);

    const int ty = tid >> 4, tx = tid & 15, c0 = tx * 8;
    #pragma unroll
    for (int i = 0; i < 4; ++i) {
        int row = base + ty * 4 + i;
        if (row < n) {
            #pragma unroll
            for (int j = 0; j < 8; ++j)
                g_h[(size_t)row * HH + c0 + j] = fmaxf(acc[i][j] + b1[c0 + j], 0.f);
        }
    }
}

// ---------------- P = BN?(h) @ W1a_top : bf16 mma, fused BN -------------------
__global__ void __launch_bounds__(NT, 3) k_precompute(
    const float* __restrict__ W,
    const float* __restrict__ gamma, const float* __restrict__ beta,
    int bnl, int n, int ntiles)
{
    extern __shared__ float smem[];
    unsigned* Wf = (unsigned*)smem;                      // 64*132 uints
    __nv_bfloat16* As = (__nv_bfloat16*)(Wf + 64 * 132); // 64 rows x 136 bf16
    float* sc = (float*)(As + 64 * 136);                 // 128
    float* sh = sc + 128;                                // 128
    const int tid  = threadIdx.x;
    const int lane = tid & 31, w = tid >> 5;
    const int q = w & 3, h = w >> 2;
    const int g2 = lane >> 2, tg = lane & 3;

    stage_w_bf16(Wf, W, 8, tid);
    if (tid < 128) {
        if (bnl >= 0) {
            float invn = 1.f / (float)n;
            float mu  = g_sum[bnl * HH + tid] * invn;
            float var = g_sq[bnl * HH + tid] * invn - mu * mu;
            float s = gamma[tid] * rsqrtf(var + EPSBN);
            sc[tid] = s; sh[tid] = beta[tid] - mu * s;
        } else { sc[tid] = 1.f; sh[tid] = 0.f; }
    }
    const unsigned alane = a_lane_addr_bf(As, q, lane);

    for (int tile = blockIdx.x; tile < ntiles; tile += gridDim.x) {
        const int base = tile * 64;
        __syncthreads();
        // producer: 64 rows x 16 chunks of 8 cols, 4 items/thread
        for (int wi = tid; wi < 1024; wi += NT) {
            int row = wi & 63, c = wi >> 6, j = c * 8;
            int node = base + row;
            float v[8] = {0,0,0,0,0,0,0,0};
            if (node < n) {
                float4 va, vb;
                if (bnl >= 0) {
                    va = *(const float4*)(g_r + (size_t)node * HH + j);
                    vb = *(const float4*)(g_r + (size_t)node * HH + j + 4);
                    v[0] = va.x * sc[j+0] + sh[j+0]; v[1] = va.y * sc[j+1] + sh[j+1];
                    v[2] = va.z * sc[j+2] + sh[j+2]; v[3] = va.w * sc[j+3] + sh[j+3];
                    v[4] = vb.x * sc[j+4] + sh[j+4]; v[5] = vb.y * sc[j+5] + sh[j+5];
                    v[6] = vb.z * sc[j+6] + sh[j+6]; v[7] = vb.w * sc[j+7] + sh[j+7];
                    *(float4*)(g_h + (size_t)node * HH + j)     = make_float4(v[0],v[1],v[2],v[3]);
                    *(float4*)(g_h + (size_t)node * HH + j + 4) = make_float4(v[4],v[5],v[6],v[7]);
                } else {
                    va = *(const float4*)(g_h + (size_t)node * HH + j);
                    vb = *(const float4*)(g_h + (size_t)node * HH + j + 4);
                    v[0]=va.x; v[1]=va.y; v[2]=va.z; v[3]=va.w;
                    v[4]=vb.x; v[5]=vb.y; v[6]=vb.z; v[7]=vb.w;
                }
            }
            unsigned outw[4];
            #pragma unroll
            for (int s = 0; s < 4; ++s) {
                __nv_bfloat162 mb = __floats2bfloat162_rn(v[2*s], v[2*s+1]);
                outw[s] = *(unsigned*)&mb;
            }
            *(uint4*)(As + row * 136 + j) = *(uint4*)outw;
        }
        __syncthreads();

        float acc[8][4] = {};
        #pragma unroll
        for (int ks = 0; ks < 8; ++ks) {
            uint4 a = ldsm4(alane + ks * 32);
            #pragma unroll
            for (int pp = 0; pp < 4; ++pp) {
                uint4 b = *(const uint4*)(Wf + ((h * 8 + ks) * 4 + pp) * 132 + lane * 4);
                mma16(acc[2 * pp],     a, b.x, b.y);
                mma16(acc[2 * pp + 1], a, b.z, b.w);
            }
        }
        int r0 = base + q * 16 + g2;
        #pragma unroll
        for (int nt = 0; nt < 8; ++nt) {
            int col = h * 64 + 8 * nt + 2 * tg;
            if (r0 < n) {
                __nv_bfloat162 pv = __floats2bfloat162_rn(acc[nt][0], acc[nt][1]);
                g_pb[(size_t)r0 * 64 + (col >> 1)] = *(unsigned*)&pv;
            }
            if (r0 + 8 < n) {
                __nv_bfloat162 pv = __floats2bfloat162_rn(acc[nt][2], acc[nt][3]);
                g_pb[(size_t)(r0 + 8) * 64 + (col >> 1)] = *(unsigned*)&pv;
            }
        }
    }
}

// ---------------- edge kernel: bf16 mma, occ 3/SM ------------------------------
__global__ void __launch_bounds__(NT, 3) k_edge(
    const float* __restrict__ ea,
    const int* __restrict__ src, const int* __restrict__ dst,
    const float* __restrict__ Wtail,
    const float* __restrict__ b1a,
    const float* __restrict__ W1b, const float* __restrict__ b1b,
    int E, int ntiles)
{
    extern __shared__ float smem[];
    unsigned* Wf = (unsigned*)smem;                      // 64*132 uints
    __nv_bfloat16* As = (__nv_bfloat16*)(Wf + 64 * 132); // 64 x 136 bf16
    float* wt  = (float*)(As + 64 * 136);                // 2*128
    float* bs  = wt + 256;                               // b1a
    float* b2s = bs + 128;                               // b1b
    float* eas = b2s + 128;                              // 2*64
    int*   sd  = (int*)(eas + 128);                      // src 64 | dst 64

    const int tid  = threadIdx.x;
    const int lane = tid & 31, w = tid >> 5;
    const int q = w & 3, h = w >> 2;
    const int g2 = lane >> 2, tg = lane & 3;

    stage_w_bf16(Wf, W1b, 8, tid);
    for (int t = tid; t < 256; t += NT) wt[t] = Wtail[t];
    if (tid < 128) { bs[tid] = b1a[tid]; b2s[tid] = b1b[tid]; }
    const unsigned alane = a_lane_addr_bf(As, q, lane);

    for (int tile = blockIdx.x; tile < ntiles; tile += gridDim.x) {
        const int e0 = tile * 64;
        __syncthreads();
        if (tid < 64) {
            int e = e0 + tid;
            if (e < E) {
                sd[tid]      = src[e];
                sd[64 + tid] = dst[e];
                eas[2 * tid]     = ea[(size_t)e * 2];
                eas[2 * tid + 1] = ea[(size_t)e * 2 + 1];
            } else {
                sd[tid] = 0; sd[64 + tid] = -1;
                eas[2 * tid] = 0.f; eas[2 * tid + 1] = 0.f;
            }
        }
        __syncthreads();

        // producer: gather bf16 P + rank-2 + bias + ReLU -> bf16 row-major tile
        for (int wi = tid; wi < 1024; wi += NT) {
            int row = wi & 63, c = wi >> 6, j = c * 8;
            uint4 p8 = ((const uint4*)(g_pb + (size_t)sd[row] * 64))[c];
            float ev0 = eas[2 * row], ev1 = eas[2 * row + 1];
            unsigned pw[4] = {p8.x, p8.y, p8.z, p8.w};
            unsigned outw[4];
            #pragma unroll
            for (int s = 0; s < 4; ++s) {
                float2 pf = __bfloat1622float2(*(__nv_bfloat162*)&pw[s]);
                int jj = j + 2 * s;
                float m0 = fmaf(ev0, wt[jj],   fmaf(ev1, wt[128 + jj],   pf.x + bs[jj]));
                float m1 = fmaf(ev0, wt[jj+1], fmaf(ev1, wt[128 + jj+1], pf.y + bs[jj+1]));
                __nv_bfloat162 mb = __floats2bfloat162_rn(fmaxf(m0, 0.f), fmaxf(m1, 0.f));
                outw[s] = *(unsigned*)&mb;
            }
            *(uint4*)(As + row * 136 + j) = *(uint4*)outw;
        }
        __syncthreads();

        float acc[8][4] = {};
        #pragma unroll
        for (int ks = 0; ks < 8; ++ks) {
            uint4 a = ldsm4(alane + ks * 32);
            #pragma unroll
            for (int pp = 0; pp < 4; ++pp) {
                uint4 b = *(const uint4*)(Wf + ((h * 8 + ks) * 4 + pp) * 132 + lane * 4);
                mma16(acc[2 * pp],     a, b.x, b.y);
                mma16(acc[2 * pp + 1], a, b.z, b.w);
            }
        }

        // bias + ReLU + red.v2 scatter directly from accumulators
        int d0 = sd[64 + q * 16 + g2];
        int d1 = sd[64 + q * 16 + g2 + 8];
        #pragma unroll
        for (int nt = 0; nt < 8; ++nt) {
            int col = h * 64 + 8 * nt + 2 * tg;
            float bb0 = b2s[col], bb1 = b2s[col + 1];
            if (d0 >= 0) {
                float v0 = fmaxf(acc[nt][0] + bb0, 0.f);
                float v1 = fmaxf(acc[nt][1] + bb1, 0.f);
                asm volatile("red.global.add.v2.f32 [%0], {%1,%2};"
                             :: "l"(g_agg + (size_t)d0 * HH + col), "f"(v0), "f"(v1)
                             : "memory");
            }
            if (d1 >= 0) {
                float v2 = fmaxf(acc[nt][2] + bb0, 0.f);
                float v3 = fmaxf(acc[nt][3] + bb1, 0.f);
                asm volatile("red.global.add.v2.f32 [%0], {%1,%2};"
                             :: "l"(g_agg + (size_t)d1 * HH + col), "f"(v2), "f"(v3)
                             : "memory");
            }
        }
    }
}

// ---------------- update1: U = relu([h | agg/deg] @ W2a + b2a) (tf32) --------
__global__ void __launch_bounds__(NT, 1) k_update1(
    const float* __restrict__ W2a, const float* __restrict__ b2a,
    int n, int ntiles, int zero_agg)
{
    extern __shared__ float smem[];
    float* Wf   = smem;                // 256*132
    float* As   = Wf + 256 * 132;      // 64*260 row-major (K=256)
    float* sinv = As + 64 * 260;       // 64
    const int tid  = threadIdx.x;
    const int lane = tid & 31, w = tid >> 5;
    const int q = w & 3, h = w >> 2;
    const int g = lane >> 2, tg = lane & 3;

    stage_w_frag(Wf, W2a, 32, tid);
    float bv[16];
    #pragma unroll
    for (int nt = 0; nt < 8; ++nt) {
        int col = h * 64 + 8 * nt + 2 * tg;
        bv[2 * nt]     = b2a[col];
        bv[2 * nt + 1] = b2a[col + 1];
    }
    const unsigned alane = a_lane_addr(As, 260, q, lane);

    for (int tile = blockIdx.x; tile < ntiles; tile += gridDim.x) {
        const int base = tile * 64;
        __syncthreads();
        if (tid < 64) {
            int node = base + tid;
            sinv[tid] = (node < n) ? 1.f / fmaxf((float)g_cnt[node], 1.f) : 0.f;
        }
        __syncthreads();

        for (int wi = tid; wi < 4096; wi += NT) {
            int row = wi >> 6, j = (wi & 63) << 2;
            int node = base + row;
            float4 v = make_float4(0.f, 0.f, 0.f, 0.f);
            if (node < n) {
                if (j < 128) {
                    v = *(const float4*)(g_h + (size_t)node * HH + j);
                } else {
                    v = *(const float4*)(g_agg + (size_t)node * HH + (j - 128));
                    float iv = sinv[row];
                    v.x *= iv; v.y *= iv; v.z *= iv; v.w *= iv;
                    if (zero_agg)
                        *(float4*)(g_agg + (size_t)node * HH + (j - 128)) =
                            make_float4(0.f, 0.f, 0.f, 0.f);
                }
            }
            uint4 st = make_uint4(f2tf32(v.x), f2tf32(v.y), f2tf32(v.z), f2tf32(v.w));
            *(uint4*)(As + row * 260 + j) = st;
        }
        __syncthreads();

        float acc[8][4] = {};
        #pragma unroll
        for (int ks = 0; ks < 32; ++ks) {
            uint4 a = ldsm4(alane + (ks << 5));
            #pragma unroll
            for (int p = 0; p < 4; ++p) {
                uint4 b = *(const uint4*)(Wf + ((h * 32 + ks) * 4 + p) * 132 + lane * 4);
                mma8(acc[2 * p],     a, b.x, b.y);
                mma8(acc[2 * p + 1], a, b.z, b.w);
            }
        }

        int r0 = base + q * 16 + g;
        #pragma unroll
        for (int nt = 0; nt < 8; ++nt) {
            int col = h * 64 + 8 * nt + 2 * tg;
            if (r0 < n)
                *(float2*)(g_u + (size_t)r0 * HH + col) =
                    make_float2(fmaxf(acc[nt][0] + bv[2 * nt], 0.f),
                                fmaxf(acc[nt][1] + bv[2 * nt + 1], 0.f));
            if (r0 + 8 < n)
                *(float2*)(g_u + (size_t)(r0 + 8) * HH + col) =
                    make_float2(fmaxf(acc[nt][2] + bv[2 * nt], 0.f),
                                fmaxf(acc[nt][3] + bv[2 * nt + 1], 0.f));
        }
    }
}

// ---------------- update2: out=sigmoid(U@W2b+b), r=h+out, BN stats (tf32) ----
__global__ void __launch_bounds__(NT, 2) k_update2(
    const float* __restrict__ W2b, const float* __restrict__ b2b,
    int l, int n, int ntiles)
{
    extern __shared__ float smem[];
    float* Wf = smem;               // 128*132
    float* As = Wf + 128 * 132;     // 64*132 (A fragments, then r tile)
    const int tid  = threadIdx.x;
    const int lane = tid & 31, w = tid >> 5;
    const int q = w & 3, h = w >> 2;
    const int g = lane >> 2, tg = lane & 3;

    stage_w_frag(Wf, W2b, 16, tid);
    float bv[16];
    #pragma unroll
    for (int nt = 0; nt < 8; ++nt) {
        int col = h * 64 + 8 * nt + 2 * tg;
        bv[2 * nt]     = b2b[col];
        bv[2 * nt + 1] = b2b[col + 1];
    }
    const unsigned alane = a_lane_addr(As, 132, q, lane);

    for (int tile = blockIdx.x; tile < ntiles; tile += gridDim.x) {
        const int base = tile * 64;
        __syncthreads();
        for (int wi = tid; wi < 2048; wi += NT) {
            int row = wi >> 5, j = (wi & 31) << 2;
            float4 v = make_float4(0.f, 0.f, 0.f, 0.f);
            if (base + row < n)
                v = *(const float4*)(g_u + (size_t)(base + row) * HH + j);
            uint4 st = make_uint4(f2tf32(v.x), f2tf32(v.y), f2tf32(v.z), f2tf32(v.w));
            *(uint4*)(As + row * 132 + j) = st;
        }
        __syncthreads();

        float acc[8][4] = {};
        #pragma unroll
        for (int ks = 0; ks < 16; ++ks) {
            uint4 a = ldsm4(alane + (ks << 5));
            #pragma unroll
            for (int p = 0; p < 4; ++p) {
                uint4 b = *(const uint4*)(Wf + ((h * 16 + ks) * 4 + p) * 132 + lane * 4);
                mma8(acc[2 * p],     a, b.x, b.y);
                mma8(acc[2 * p + 1], a, b.z, b.w);
            }
        }
        __syncthreads();   // ldsm reads done -> reuse As as r tile

        int r0 = base + q * 16 + g;
        #pragma unroll
        for (int nt = 0; nt < 8; ++nt) {
            int col = h * 64 + 8 * nt + 2 * tg;
            float2 rv0 = make_float2(0.f, 0.f), rv1 = make_float2(0.f, 0.f);
            if (r0 < n) {
                float2 hv = *(const float2*)(g_h + (size_t)r0 * HH + col);
                rv0.x = hv.x + 1.f / (1.f + expf(-(acc[nt][0] + bv[2 * nt])));
                rv0.y = hv.y + 1.f / (1.f + expf(-(acc[nt][1] + bv[2 * nt + 1])));
            }
            if (r0 + 8 < n) {
                float2 hv = *(const float2*)(g_h + (size_t)(r0 + 8) * HH + col);
                rv1.x = hv.x + 1.f / (1.f + expf(-(acc[nt][2] + bv[2 * nt])));
                rv1.y = hv.y + 1.f / (1.f + expf(-(acc[nt][3] + bv[2 * nt + 1])));
            }
            *(float2*)(As + (q * 16 + g) * 132 + col)     = rv0;
            *(float2*)(As + (q * 16 + g + 8) * 132 + col) = rv1;
        }
        __syncthreads();

        for (int wi = tid; wi < 2048; wi += NT) {
            int row = wi >> 5, j = (wi & 31) << 2;
            if (base + row < n) {
                float4 v = *(const float4*)(As + row * 132 + j);
                *(float4*)(g_r + (size_t)(base + row) * HH + j) = v;
            }
        }
        {
            int c = tid & 127, half = tid >> 7;
            float s = 0.f, s2 = 0.f;
            #pragma unroll 8
            for (int r = half * 32; r < half * 32 + 32; ++r) {
                float v = As[r * 132 + c];
                s += v; s2 += v * v;
            }
            atomicAdd(&g_sum[l * HH + c], s);
            atomicAdd(&g_sq[l * HH + c],  s2);
        }
    }
}

// ---------------- final MLP with fused BN(layer 2) ----------------------------
__global__ __launch_bounds__(NT) void k_final(
    const float* __restrict__ Wf, const float* __restrict__ bf,
    const float* __restrict__ Wo, const float* __restrict__ bo,
    const float* __restrict__ gamma, const float* __restrict__ beta,
    int bnl, float* __restrict__ out, int n)
{
    extern __shared__ float smem[];
    float* As = smem;
    float* Ws = As + 64 * 132;
    float* sc = Ws + 2048;
    float* sh = sc + 128;
    const int tid = threadIdx.x;
    const int base = blockIdx.x * 64;

    if (tid < 128) {
        float invn = 1.f / (float)n;
        float mu  = g_sum[bnl * HH + tid] * invn;
        float var = g_sq[bnl * HH + tid] * invn - mu * mu;
        float s = gamma[tid] * rsqrtf(var + EPSBN);
        sc[tid] = s; sh[tid] = beta[tid] - mu * s;
    }
    __syncthreads();

    for (int t = tid; t < 64 * 32; t += NT) {
        int row = t >> 5, j = (t & 31) << 2;
        float4 v = make_float4(0.f, 0.f, 0.f, 0.f);
        if (base + row < n) {
            v = *(const float4*)(g_r + (size_t)(base + row) * HH + j);
            v.x = v.x * sc[j + 0] + sh[j + 0];
            v.y = v.y * sc[j + 1] + sh[j + 1];
            v.z = v.z * sc[j + 2] + sh[j + 2];
            v.w = v.w * sc[j + 3] + sh[j + 3];
        }
        *(float4*)(As + row * 132 + j) = v;
    }

    float acc[4][8] = {};
    gemm_acc<4>(As, 132, Ws, Wf, HH, acc, tid);

    const int ty = tid >> 4, tx = tid & 15, c0 = tx * 8;
    #pragma unroll
    for (int i = 0; i < 4; ++i)
        #pragma unroll
        for (int j = 0; j < 8; ++j)
            As[(ty * 4 + i) * 132 + c0 + j] = fmaxf(acc[i][j] + bf[c0 + j], 0.f);
    __syncthreads();

    const int w = tid >> 5, lane = tid & 31;
    #pragma unroll
    for (int rr = 0; rr < 8; ++rr) {
        int row = w * 8 + rr;
        float sAcc = 0.f;
        #pragma unroll
        for (int qq = 0; qq < 4; ++qq)
            sAcc += As[row * 132 + lane + 32 * qq] * Wo[lane + 32 * qq];
        #pragma unroll
        for (int off = 16; off; off >>= 1)
            sAcc += __shfl_xor_sync(0xffffffffu, sAcc, off);
        if (lane == 0 && base + row < n)
            out[base + row] = 1.f / (1.f + expf(-sAcc));
    }
}

// ---------------- launcher -----------------------------------------------------
extern "C" void kernel_launch(void* const* d_in, const int* in_sizes, int n_in,
                              void* d_out, int out_size)
{
    const float* x    = (const float*)d_in[0];
    const float* ea   = (const float*)d_in[1];
    const int*   ei   = (const int*)  d_in[2];
    const float* W0   = (const float*)d_in[4];
    const float* b0   = (const float*)d_in[5];
    const float* W1   = (const float*)d_in[6];
    const float* b1   = (const float*)d_in[7];
    const float* W1a  = (const float*)d_in[8];
    const float* b1a  = (const float*)d_in[9];
    const float* W1b  = (const float*)d_in[10];
    const float* b1b  = (const float*)d_in[11];
    const float* W2a  = (const float*)d_in[12];
    const float* b2a  = (const float*)d_in[13];
    const float* W2b  = (const float*)d_in[14];
    const float* b2b  = (const float*)d_in[15];
    const float* gam  = (const float*)d_in[16];
    const float* bet  = (const float*)d_in[17];
    const float* Wf   = (const float*)d_in[18];
    const float* bf   = (const float*)d_in[19];
    const float* Wo   = (const float*)d_in[20];
    const float* bo   = (const float*)d_in[21];
    float* out = (float*)d_out;

    const int n = in_sizes[0] / 2;
    const int E = in_sizes[2] / 2;
    const int* srcp = ei;
    const int* dstp = ei + E;

    const int nb_n     = (n + 63) / 64;
    const int ntiles_n = nb_n;
    const int ntiles_e = (E + 63) / 64;
    const int gPers2   = 296;   // 2 blocks/SM persistent (tf32 kernels)
    const int gPers3   = 444;   // 3 blocks/SM persistent (bf16 kernels)
    const int gPers1   = 148;

    const size_t SM_IN = (size_t)(64 * 132 + 2048 + 256 + 128 + 128) * 4;
    const size_t SM_P  = (size_t)(64 * 132) * 4 + (size_t)(64 * 136) * 2
                         + 256 * 4;                                          // 52224
    const size_t SM_E  = (size_t)(64 * 132) * 4 + (size_t)(64 * 136) * 2
                         + (256 + 128 + 128 + 128 + 128) * 4;                // 54272
    const size_t SM_U1 = (size_t)(256 * 132 + 64 * 260 + 64) * 4;            // 201984
    const size_t SM_U2 = (size_t)(128 * 132 + 64 * 132) * 4;                 // 101376
    const size_t SM_F  = (size_t)(64 * 132 + 2048 + 256) * 4;

    cudaFuncSetAttribute(k_edge, cudaFuncAttributeMaxDynamicSharedMemorySize, (int)SM_E);
    cudaFuncSetAttribute(k_precompute, cudaFuncAttributeMaxDynamicSharedMemorySize, (int)SM_P);
    cudaFuncSetAttribute(k_update1, cudaFuncAttributeMaxDynamicSharedMemorySize, (int)SM_U1);
    cudaFuncSetAttribute(k_update2, cudaFuncAttributeMaxDynamicSharedMemorySize, (int)SM_U2);

    k_zero<<<1024, 256>>>(n);
    k_input<<<nb_n, NT, SM_IN>>>(x, W0, b0, W1, b1, dstp, E, n);

    for (int l = 0; l < LL; ++l) {
        const float* W1a_l  = W1a + (size_t)l * 130 * 128;
        const float* W1a_t  = W1a_l + 128 * 128;
        const float* b1a_l  = b1a + (size_t)l * 128;
        const float* W1b_l  = W1b + (size_t)l * 128 * 128;
        const float* b1b_l  = b1b + (size_t)l * 128;
        const float* W2a_l  = W2a + (size_t)l * 256 * 128;
        const float* b2a_l  = b2a + (size_t)l * 128;
        const float* W2b_l  = W2b + (size_t)l * 128 * 128;
        const float* b2b_l  = b2b + (size_t)l * 128;
        const float* gam_p  = (l > 0) ? gam + (size_t)(l - 1) * 128 : gam;
        const float* bet_p  = (l > 0) ? bet + (size_t)(l - 1) * 128 : bet;

        k_precompute<<<gPers3, NT, SM_P>>>(W1a_l, gam_p, bet_p, l - 1, n, ntiles_n);
        k_edge<<<gPers3, NT, SM_E>>>(ea, srcp, dstp, W1a_t, b1a_l, W1b_l, b1b_l,
                                     E, ntiles_e);
        k_update1<<<gPers1, NT, SM_U1>>>(W2a_l, b2a_l, n, ntiles_n,
                                         (l < LL - 1) ? 1 : 0);
        k_update2<<<gPers2, NT, SM_U2>>>(W2b_l, b2b_l, l, n, ntiles_n);
    }

    k_final<<<nb_n, NT, SM_F>>>(Wf, bf, Wo, bo,
                                gam + (size_t)(LL - 1) * 128,
                                bet + (size_t)(LL - 1) * 128,
                                LL - 1, out, n);
}

// round 7
// speedup vs baseline: 1.4870x; 1.2234x over previous
#include <cuda_runtime.h>
#include <cuda_bf16.h>
#include <math.h>
#include <stdint.h>

#define NN 50000
#define EE 800000
#define HH 128
#define LL 3
#define NT 256
#define EPSBN 1e-5f

// ---------------- scratch ---------------------------------------------------
__device__ float    g_h[NN * HH];
__device__ unsigned g_pb[NN * 64];     // P in bf16x2
__device__ float    g_agg[NN * HH];
__device__ float    g_u[NN * HH];
__device__ float    g_r[NN * HH];
__device__ int      g_cnt[NN];
__device__ int      g_fill[NN];
__device__ int      g_eoff[NN + 1];
__device__ int      g_esrc[EE];
__device__ int      g_edst[EE];
__device__ float2   g_eea[EE];
__device__ float    g_sum[LL * HH];
__device__ float    g_sq[LL * HH];

// ---------------- mma / ldmatrix helpers -------------------------------------
__device__ __forceinline__ unsigned f2tf32(float f) {
    unsigned u;
    asm("cvt.rna.tf32.f32 %0, %1;" : "=r"(u) : "f"(f));
    return u;
}
__device__ __forceinline__ void mma8(float acc[4], const uint4& a,
                                     unsigned b0, unsigned b1) {
    asm volatile(
        "mma.sync.aligned.m16n8k8.row.col.f32.tf32.tf32.f32 "
        "{%0,%1,%2,%3},{%4,%5,%6,%7},{%8,%9},{%0,%1,%2,%3};\n"
        : "+f"(acc[0]), "+f"(acc[1]), "+f"(acc[2]), "+f"(acc[3])
        : "r"(a.x), "r"(a.y), "r"(a.z), "r"(a.w), "r"(b0), "r"(b1));
}
__device__ __forceinline__ void mma16(float acc[4], const uint4& a,
                                      unsigned b0, unsigned b1) {
    asm volatile(
        "mma.sync.aligned.m16n8k16.row.col.f32.bf16.bf16.f32 "
        "{%0,%1,%2,%3},{%4,%5,%6,%7},{%8,%9},{%0,%1,%2,%3};\n"
        : "+f"(acc[0]), "+f"(acc[1]), "+f"(acc[2]), "+f"(acc[3])
        : "r"(a.x), "r"(a.y), "r"(a.z), "r"(a.w), "r"(b0), "r"(b1));
}
__device__ __forceinline__ uint4 ldsm4(unsigned addr) {
    uint4 r;
    asm volatile("ldmatrix.sync.aligned.m8n8.x4.shared.b16 {%0,%1,%2,%3}, [%4];"
        : "=r"(r.x), "=r"(r.y), "=r"(r.z), "=r"(r.w) : "r"(addr));
    return r;
}
__device__ __forceinline__ unsigned a_lane_addr(const float* As, int lda,
                                                int q, int lane) {
    return (unsigned)__cvta_generic_to_shared(As)
         + ((((q * 16 + (lane & 15)) * lda) + 4 * (lane >> 4)) << 2);
}
// bf16 row-major A tile, stride in BYTES
__device__ __forceinline__ unsigned a_lane_addr_bf(const void* As, int strideB,
                                                   int q, int lane) {
    return (unsigned)__cvta_generic_to_shared(As)
         + (q * 16 + (lane & 7) + 8 * ((lane >> 3) & 1)) * strideB
         + (lane >> 4) * 16;
}

// KxN(128) fp32 weight -> tf32 B fragments
__device__ __forceinline__ void stage_w_frag(float* Wf, const float* __restrict__ Wg,
                                             int KS, int tid)
{
    const int total = 2 * KS * 4 * 132;
    for (int i = tid; i < total; i += NT) {
        int grp = i / 132, off = i % 132;
        if (off < 128) {
            int s = off & 3, t = off >> 2;
            int gg = t >> 2, tt = t & 3;
            int hh = grp / (KS * 4);
            int rem = grp - hh * (KS * 4);
            int ks = rem >> 2, p = rem & 3;
            int k = 8 * ks + tt + ((s & 1) ? 4 : 0);
            int n = hh * 64 + 16 * p + gg + ((s >= 2) ? 8 : 0);
            Wf[i] = __uint_as_float(f2tf32(Wg[(size_t)k * 128 + n]));
        }
    }
}
// KxN(128) fp32 weight -> bf16 B fragments (k16 steps)
__device__ __forceinline__ void stage_w_bf16(unsigned* Wf, const float* __restrict__ Wg,
                                             int KS, int tid)
{
    const int total = 2 * KS * 4 * 132;
    for (int i = tid; i < total; i += NT) {
        int grp = i / 132, off = i % 132;
        if (off < 128) {
            int s = off & 3, lane = off >> 2;
            int g = lane >> 2, t = lane & 3;
            int hh = grp / (KS * 4);
            int rem = grp - hh * (KS * 4);
            int ks = rem >> 2, pp = rem & 3;
            int p = 2 * pp + (s >> 1);
            int bsel = s & 1;
            int n = hh * 64 + p * 8 + g;
            int k0 = ks * 16 + 2 * t + 8 * bsel;
            __nv_bfloat162 v = __floats2bfloat162_rn(Wg[(size_t)k0 * 128 + n],
                                                     Wg[(size_t)(k0 + 1) * 128 + n]);
            Wf[i] = *(unsigned*)&v;
        }
    }
}

// ---------------- streamed-W fp32 GEMM core (k_input / k_final) -------------
template<int RPT>
__device__ __forceinline__ void gemm_acc(const float* As, int lda, float* Ws,
                                         const float* __restrict__ Wg, int K,
                                         float acc[RPT][8], int tid)
{
    const int ty = tid >> 4, tx = tid & 15;
    for (int kc = 0; kc < K; kc += 16) {
        __syncthreads();
        for (int t = tid; t < 512; t += NT) {
            int kk = t >> 5, j4 = (t & 31) << 2;
            *(float4*)(Ws + kk * HH + j4) =
                *(const float4*)(Wg + (size_t)(kc + kk) * HH + j4);
        }
        __syncthreads();
        #pragma unroll
        for (int k = 0; k < 16; ++k) {
            float a[RPT];
            #pragma unroll
            for (int i = 0; i < RPT; ++i) a[i] = As[(ty * RPT + i) * lda + kc + k];
            float4 b0 = *(const float4*)(Ws + k * HH + tx * 8);
            float4 b1 = *(const float4*)(Ws + k * HH + tx * 8 + 4);
            float bb[8] = {b0.x, b0.y, b0.z, b0.w, b1.x, b1.y, b1.z, b1.w};
            #pragma unroll
            for (int i = 0; i < RPT; ++i)
                #pragma unroll
                for (int j = 0; j < 8; ++j)
                    acc[i][j] = fmaf(a[i], bb[j], acc[i][j]);
        }
    }
    __syncthreads();
}

// ---------------- zero init --------------------------------------------------
__global__ void k_zero(int n)
{
    int total = n * HH;
    for (int i = blockIdx.x * blockDim.x + threadIdx.x; i < total;
         i += gridDim.x * blockDim.x) {
        g_agg[i] = 0.f;
        if (i < n) { g_cnt[i] = 0; g_fill[i] = 0; }
        if (i < LL * HH) { g_sum[i] = 0.f; g_sq[i] = 0.f; }
    }
}

// ---------------- single-block inclusive scan -> exclusive offsets ----------
__global__ void k_scan(int n)
{
    __shared__ int buf[1024];
    __shared__ int carrys;
    int tid = threadIdx.x;
    if (tid == 0) carrys = 0;
    __syncthreads();
    for (int base = 0; base < n; base += 1024) {
        int v = (base + tid < n) ? g_cnt[base + tid] : 0;
        buf[tid] = v;
        __syncthreads();
        for (int off = 1; off < 1024; off <<= 1) {
            int t = (tid >= off) ? buf[tid - off] : 0;
            __syncthreads();
            buf[tid] += t;
            __syncthreads();
        }
        if (base + tid < n) g_eoff[base + tid] = carrys + buf[tid] - v;
        int tot = buf[1023];
        __syncthreads();
        if (tid == 0) carrys += tot;
        __syncthreads();
    }
    if (tid == 0) g_eoff[n] = carrys;
}

// ---------------- counting-sort scatter --------------------------------------
__global__ void k_sort(const int* __restrict__ src, const int* __restrict__ dst,
                       const float* __restrict__ ea, int E)
{
    int e = blockIdx.x * blockDim.x + threadIdx.x;
    if (e < E) {
        int d = dst[e];
        int slot = g_eoff[d] + atomicAdd(&g_fill[d], 1);
        g_esrc[slot] = src[e];
        g_edst[slot] = d;
        g_eea[slot] = make_float2(ea[2 * e], ea[2 * e + 1]);
    }
}

// ---------------- input MLP + degree count -----------------------------------
__global__ __launch_bounds__(NT) void k_input(
    const float* __restrict__ x,
    const float* __restrict__ W0, const float* __restrict__ b0,
    const float* __restrict__ W1, const float* __restrict__ b1,
    const int* __restrict__ dst, int E, int n)
{
    extern __shared__ float smem[];
    float* As  = smem;
    float* Ws  = As + 64 * 132;
    float* w0s = Ws + 2048;
    float* b0s = w0s + 256;
    float* xs  = b0s + 128;
    const int tid = threadIdx.x;
    const int base = blockIdx.x * 64;

    for (int e = blockIdx.x * blockDim.x + tid; e < E; e += gridDim.x * blockDim.x)
        atomicAdd(&g_cnt[dst[e]], 1);

    for (int t = tid; t < 256; t += NT) w0s[t] = W0[t];
    for (int t = tid; t < 128; t += NT) b0s[t] = b0[t];
    if (tid < 128) {
        int row = tid >> 1;
        xs[tid] = (base + row < n) ? x[(size_t)(base + row) * 2 + (tid & 1)] : 0.f;
    }
    __syncthreads();

    for (int t = tid; t < 64 * 32; t += NT) {
        int row = t >> 5, j = (t & 31) << 2;
        float x0 = xs[row * 2], x1 = xs[row * 2 + 1];
        float4 v;
        v.x = fmaxf(fmaf(x0, w0s[j + 0], fmaf(x1, w0s[128 + j + 0], b0s[j + 0])), 0.f);
        v.y = fmaxf(fmaf(x0, w0s[j + 1], fmaf(x1, w0s[128 + j + 1], b0s[j + 1])), 0.f);
        v.z = fmaxf(fmaf(x0, w0s[j + 2], fmaf(x1, w0s[128 + j + 2], b0s[j + 2])), 0.f);
        v.w = fmaxf(fmaf(x0, w0s[j + 3], fmaf(x1, w0s[128 + j + 3], b0s[j + 3])), 0.f);
        *(float4*)(As + row * 132 + j) = v;
    }

    float acc[4][8] = {};
    gemm_acc<4>(As, 132, Ws, W1, HH, acc, tid);

    const int ty = tid >> 4, tx = tid & 15, c0 = tx * 8;
    #pragma unroll
    for (int i = 0; i < 4; ++i) {
        int row = base + ty * 4 + i;
        if (row < n) {
            #pragma unroll
            for (int j = 0; j < 8; ++j)
                g_h[(size_t)row * HH + c0 + j] = fmaxf(acc[i][j] + b1[c0 + j], 0.f);
        }
    }
}

// ---------------- P = BN?(h) @ W1a_top : bf16 mma, fused BN -------------------
__global__ void __launch_bounds__(NT, 3) k_precompute(
    const float* __restrict__ W,
    const float* __restrict__ gamma, const float* __restrict__ beta,
    int bnl, int n, int ntiles)
{
    extern __shared__ float smem[];
    unsigned* Wf = (unsigned*)smem;                      // 8448 words
    __nv_bfloat16* As = (__nv_bfloat16*)(Wf + 8448);     // 64 x 136 bf16
    float* scp = (float*)(As + 64 * 136);                // 144
    float* shp = scp + 144;                              // 144
    const int tid  = threadIdx.x;
    const int lane = tid & 31, w = tid >> 5;
    const int q = w & 3, h = w >> 2;
    const int g2 = lane >> 2, tg = lane & 3;

    stage_w_bf16(Wf, W, 8, tid);
    if (tid < 128) {
        int c = tid >> 3, s = tid & 7;
        if (bnl >= 0) {
            float invn = 1.f / (float)n;
            float mu  = g_sum[bnl * HH + tid] * invn;
            float var = g_sq[bnl * HH + tid] * invn - mu * mu;
            float sv = gamma[tid] * rsqrtf(var + EPSBN);
            scp[c * 9 + s] = sv; shp[c * 9 + s] = beta[tid] - mu * sv;
        } else { scp[c * 9 + s] = 1.f; shp[c * 9 + s] = 0.f; }
    }
    const unsigned alane = a_lane_addr_bf(As, 272, q, lane);
    const int pc = tid & 15;     // fixed chunk of 8 cols

    for (int tile = blockIdx.x; tile < ntiles; tile += gridDim.x) {
        const int base = tile * 64;
        __syncthreads();
        for (int wi = tid; wi < 1024; wi += NT) {
            int row = wi >> 4, j = pc * 8;
            int node = base + row;
            float v[8] = {0,0,0,0,0,0,0,0};
            if (node < n) {
                float4 va, vb;
                if (bnl >= 0) {
                    va = *(const float4*)(g_r + (size_t)node * HH + j);
                    vb = *(const float4*)(g_r + (size_t)node * HH + j + 4);
                    float vv[8] = {va.x,va.y,va.z,va.w,vb.x,vb.y,vb.z,vb.w};
                    #pragma unroll
                    for (int s = 0; s < 8; ++s)
                        v[s] = vv[s] * scp[pc * 9 + s] + shp[pc * 9 + s];
                    *(float4*)(g_h + (size_t)node * HH + j)     = make_float4(v[0],v[1],v[2],v[3]);
                    *(float4*)(g_h + (size_t)node * HH + j + 4) = make_float4(v[4],v[5],v[6],v[7]);
                } else {
                    va = *(const float4*)(g_h + (size_t)node * HH + j);
                    vb = *(const float4*)(g_h + (size_t)node * HH + j + 4);
                    v[0]=va.x; v[1]=va.y; v[2]=va.z; v[3]=va.w;
                    v[4]=vb.x; v[5]=vb.y; v[6]=vb.z; v[7]=vb.w;
                }
            }
            unsigned outw[4];
            #pragma unroll
            for (int s = 0; s < 4; ++s) {
                __nv_bfloat162 mb = __floats2bfloat162_rn(v[2*s], v[2*s+1]);
                outw[s] = *(unsigned*)&mb;
            }
            *(uint4*)(As + row * 136 + j) = *(uint4*)outw;
        }
        __syncthreads();

        float acc[8][4] = {};
        #pragma unroll
        for (int ks = 0; ks < 8; ++ks) {
            uint4 a = ldsm4(alane + ks * 32);
            #pragma unroll
            for (int pp = 0; pp < 4; ++pp) {
                uint4 b = *(const uint4*)(Wf + ((h * 8 + ks) * 4 + pp) * 132 + lane * 4);
                mma16(acc[2 * pp],     a, b.x, b.y);
                mma16(acc[2 * pp + 1], a, b.z, b.w);
            }
        }
        int r0 = base + q * 16 + g2;
        #pragma unroll
        for (int nt = 0; nt < 8; ++nt) {
            int col = h * 64 + 8 * nt + 2 * tg;
            if (r0 < n) {
                __nv_bfloat162 pv = __floats2bfloat162_rn(acc[nt][0], acc[nt][1]);
                g_pb[(size_t)r0 * 64 + (col >> 1)] = *(unsigned*)&pv;
            }
            if (r0 + 8 < n) {
                __nv_bfloat162 pv = __floats2bfloat162_rn(acc[nt][2], acc[nt][3]);
                g_pb[(size_t)(r0 + 8) * 64 + (col >> 1)] = *(unsigned*)&pv;
            }
        }
    }
}

// ---------------- edge kernel: sorted edges + segmented smem reduce ----------
__global__ void __launch_bounds__(NT, 3) k_edge(
    const float* __restrict__ Wtail,
    const float* __restrict__ b1a,
    const float* __restrict__ W1b, const float* __restrict__ b1b,
    int E, int ntiles)
{
    extern __shared__ float smem[];
    unsigned* Wf = (unsigned*)smem;                      // 8448 words
    __nv_bfloat16* As = (__nv_bfloat16*)(Wf + 8448);     // 64 x 136 bf16 (4352 w)
    float* Ds  = (float*)(As + 64 * 136);                // 32 x 132 f32 (4224 w)
    float* wt0p = Ds + 32 * 132;                         // 144
    float* wt1p = wt0p + 144;                            // 144
    float* bsp  = wt1p + 144;                            // 144
    float* b2s  = bsp + 144;                             // 128
    float* eas  = b2s + 128;                             // 128
    int*   sd   = (int*)(eas + 128);                     // 128

    const int tid  = threadIdx.x;
    const int lane = tid & 31, w = tid >> 5;
    const int q = w & 3, h = w >> 2;
    const int g2 = lane >> 2, tg = lane & 3;

    stage_w_bf16(Wf, W1b, 8, tid);
    if (tid < 128) {
        int c = tid >> 3, s = tid & 7;
        wt0p[c * 9 + s] = Wtail[tid];
        wt1p[c * 9 + s] = Wtail[128 + tid];
        bsp[c * 9 + s]  = b1a[tid];
        b2s[tid] = b1b[tid];
    }
    const unsigned alane = a_lane_addr_bf(As, 272, q, lane);
    const int pc = tid & 15;
    const int pairc = tid & 63, rg = tid >> 6;

    for (int tile = blockIdx.x; tile < ntiles; tile += gridDim.x) {
        const int e0 = tile * 64;
        __syncthreads();
        if (tid < 64) {
            int e = e0 + tid;
            if (e < E) {
                sd[tid]      = g_esrc[e];
                sd[64 + tid] = g_edst[e];
                float2 ee = g_eea[e];
                eas[2 * tid] = ee.x; eas[2 * tid + 1] = ee.y;
            } else {
                sd[tid] = 0; sd[64 + tid] = -1;
                eas[2 * tid] = 0.f; eas[2 * tid + 1] = 0.f;
            }
        }
        __syncthreads();

        // producer: coalesced gather + rank-2 + bias + ReLU -> bf16 tile
        for (int wi = tid; wi < 1024; wi += NT) {
            int row = wi >> 4, j = pc * 8;
            uint4 p8 = ((const uint4*)(g_pb + (size_t)sd[row] * 64))[pc];
            float ev0 = eas[2 * row], ev1 = eas[2 * row + 1];
            unsigned pw[4] = {p8.x, p8.y, p8.z, p8.w};
            unsigned outw[4];
            #pragma unroll
            for (int s = 0; s < 4; ++s) {
                float2 pf = __bfloat1622float2(*(__nv_bfloat162*)&pw[s]);
                float m0 = fmaf(ev0, wt0p[pc*9 + 2*s],
                                fmaf(ev1, wt1p[pc*9 + 2*s],   pf.x + bsp[pc*9 + 2*s]));
                float m1 = fmaf(ev0, wt0p[pc*9 + 2*s+1],
                                fmaf(ev1, wt1p[pc*9 + 2*s+1], pf.y + bsp[pc*9 + 2*s+1]));
                __nv_bfloat162 mb = __floats2bfloat162_rn(fmaxf(m0, 0.f), fmaxf(m1, 0.f));
                outw[s] = *(unsigned*)&mb;
            }
            *(uint4*)(As + row * 136 + j) = *(uint4*)outw;
        }
        __syncthreads();

        float acc[8][4] = {};
        #pragma unroll
        for (int ks = 0; ks < 8; ++ks) {
            uint4 a = ldsm4(alane + ks * 32);
            #pragma unroll
            for (int pp = 0; pp < 4; ++pp) {
                uint4 b = *(const uint4*)(Wf + ((h * 8 + ks) * 4 + pp) * 132 + lane * 4);
                mma16(acc[2 * pp],     a, b.x, b.y);
                mma16(acc[2 * pp + 1], a, b.z, b.w);
            }
        }

        // two-phase epilogue: stage D (32 rows) -> segmented reduce -> red.v2
        #pragma unroll
        for (int p = 0; p < 2; ++p) {
            __syncthreads();
            if ((q >> 1) == p) {
                int lr = (q & 1) * 16 + g2;
                #pragma unroll
                for (int nt = 0; nt < 8; ++nt) {
                    int col = h * 64 + 8 * nt + 2 * tg;
                    float bb0 = b2s[col], bb1 = b2s[col + 1];
                    *(float2*)(Ds + lr * 132 + col) =
                        make_float2(fmaxf(acc[nt][0] + bb0, 0.f),
                                    fmaxf(acc[nt][1] + bb1, 0.f));
                    *(float2*)(Ds + (lr + 8) * 132 + col) =
                        make_float2(fmaxf(acc[nt][2] + bb0, 0.f),
                                    fmaxf(acc[nt][3] + bb1, 0.f));
                }
            }
            __syncthreads();
            int gr = p * 32 + rg * 8;
            float2 sv = make_float2(0.f, 0.f);
            int cur = sd[64 + gr];
            #pragma unroll
            for (int r = 0; r < 8; ++r) {
                int dd = sd[64 + gr + r];
                float2 v = *(const float2*)(Ds + (rg * 8 + r) * 132 + pairc * 2);
                if (dd != cur) {
                    if (cur >= 0)
                        asm volatile("red.global.add.v2.f32 [%0], {%1,%2};"
                                     :: "l"(g_agg + (size_t)cur * HH + pairc * 2),
                                        "f"(sv.x), "f"(sv.y) : "memory");
                    sv = make_float2(0.f, 0.f);
                    cur = dd;
                }
                sv.x += v.x; sv.y += v.y;
            }
            if (cur >= 0)
                asm volatile("red.global.add.v2.f32 [%0], {%1,%2};"
                             :: "l"(g_agg + (size_t)cur * HH + pairc * 2),
                                "f"(sv.x), "f"(sv.y) : "memory");
        }
    }
}

// ---------------- update1: U = relu([h | agg/deg] @ W2a + b2a) (bf16) --------
__global__ void __launch_bounds__(NT, 2) k_update1(
    const float* __restrict__ W2a, const float* __restrict__ b2a,
    int n, int ntiles, int zero_agg)
{
    extern __shared__ float smem[];
    unsigned* Wf = (unsigned*)smem;                      // 16896 words
    __nv_bfloat16* As = (__nv_bfloat16*)(Wf + 16896);    // 64 x 264 bf16 (8448 w)
    float* sinv = (float*)(As + 64 * 264);               // 64
    const int tid  = threadIdx.x;
    const int lane = tid & 31, w = tid >> 5;
    const int q = w & 3, h = w >> 2;
    const int g = lane >> 2, tg = lane & 3;

    stage_w_bf16(Wf, W2a, 16, tid);
    float bv[16];
    #pragma unroll
    for (int nt = 0; nt < 8; ++nt) {
        int col = h * 64 + 8 * nt + 2 * tg;
        bv[2 * nt]     = b2a[col];
        bv[2 * nt + 1] = b2a[col + 1];
    }
    const unsigned alane = a_lane_addr_bf(As, 528, q, lane);
    const int cu = tid & 31;

    for (int tile = blockIdx.x; tile < ntiles; tile += gridDim.x) {
        const int base = tile * 64;
        __syncthreads();
        if (tid < 64) {
            int node = base + tid;
            sinv[tid] = (node < n) ? 1.f / fmaxf((float)g_cnt[node], 1.f) : 0.f;
        }
        __syncthreads();

        for (int wi = tid; wi < 2048; wi += NT) {
            int row = wi >> 5, j = cu * 8;
            int node = base + row;
            float v[8] = {0,0,0,0,0,0,0,0};
            if (node < n) {
                if (cu < 16) {
                    float4 va = *(const float4*)(g_h + (size_t)node * HH + j);
                    float4 vb = *(const float4*)(g_h + (size_t)node * HH + j + 4);
                    v[0]=va.x; v[1]=va.y; v[2]=va.z; v[3]=va.w;
                    v[4]=vb.x; v[5]=vb.y; v[6]=vb.z; v[7]=vb.w;
                } else {
                    int ja = j - 128;
                    float4 va = *(const float4*)(g_agg + (size_t)node * HH + ja);
                    float4 vb = *(const float4*)(g_agg + (size_t)node * HH + ja + 4);
                    float iv = sinv[row];
                    v[0]=va.x*iv; v[1]=va.y*iv; v[2]=va.z*iv; v[3]=va.w*iv;
                    v[4]=vb.x*iv; v[5]=vb.y*iv; v[6]=vb.z*iv; v[7]=vb.w*iv;
                    if (zero_agg) {
                        *(float4*)(g_agg + (size_t)node * HH + ja)     = make_float4(0,0,0,0);
                        *(float4*)(g_agg + (size_t)node * HH + ja + 4) = make_float4(0,0,0,0);
                    }
                }
            }
            unsigned outw[4];
            #pragma unroll
            for (int s = 0; s < 4; ++s) {
                __nv_bfloat162 mb = __floats2bfloat162_rn(v[2*s], v[2*s+1]);
                outw[s] = *(unsigned*)&mb;
            }
            *(uint4*)(As + row * 264 + j) = *(uint4*)outw;
        }
        __syncthreads();

        float acc[8][4] = {};
        #pragma unroll
        for (int ks = 0; ks < 16; ++ks) {
            uint4 a = ldsm4(alane + ks * 32);
            #pragma unroll
            for (int pp = 0; pp < 4; ++pp) {
                uint4 b = *(const uint4*)(Wf + ((h * 16 + ks) * 4 + pp) * 132 + lane * 4);
                mma16(acc[2 * pp],     a, b.x, b.y);
                mma16(acc[2 * pp + 1], a, b.z, b.w);
            }
        }

        int r0 = base + q * 16 + g;
        #pragma unroll
        for (int nt = 0; nt < 8; ++nt) {
            int col = h * 64 + 8 * nt + 2 * tg;
            if (r0 < n)
                *(float2*)(g_u + (size_t)r0 * HH + col) =
                    make_float2(fmaxf(acc[nt][0] + bv[2 * nt], 0.f),
                                fmaxf(acc[nt][1] + bv[2 * nt + 1], 0.f));
            if (r0 + 8 < n)
                *(float2*)(g_u + (size_t)(r0 + 8) * HH + col) =
                    make_float2(fmaxf(acc[nt][2] + bv[2 * nt], 0.f),
                                fmaxf(acc[nt][3] + bv[2 * nt + 1], 0.f));
        }
    }
}

// ---------------- update2: out=sigmoid(U@W2b+b), r=h+out, BN stats (tf32) ----
__global__ void __launch_bounds__(NT, 2) k_update2(
    const float* __restrict__ W2b, const float* __restrict__ b2b,
    int l, int n, int ntiles)
{
    extern __shared__ float smem[];
    float* Wf = smem;               // 128*132
    float* As = Wf + 128 * 132;     // 64*132 (A fragments, then r tile)
    const int tid  = threadIdx.x;
    const int lane = tid & 31, w = tid >> 5;
    const int q = w & 3, h = w >> 2;
    const int g = lane >> 2, tg = lane & 3;

    stage_w_frag(Wf, W2b, 16, tid);
    float bv[16];
    #pragma unroll
    for (int nt = 0; nt < 8; ++nt) {
        int col = h * 64 + 8 * nt + 2 * tg;
        bv[2 * nt]     = b2b[col];
        bv[2 * nt + 1] = b2b[col + 1];
    }
    const unsigned alane = a_lane_addr(As, 132, q, lane);

    for (int tile = blockIdx.x; tile < ntiles; tile += gridDim.x) {
        const int base = tile * 64;
        __syncthreads();
        for (int wi = tid; wi < 2048; wi += NT) {
            int row = wi >> 5, j = (wi & 31) << 2;
            float4 v = make_float4(0.f, 0.f, 0.f, 0.f);
            if (base + row < n)
                v = *(const float4*)(g_u + (size_t)(base + row) * HH + j);
            uint4 st = make_uint4(f2tf32(v.x), f2tf32(v.y), f2tf32(v.z), f2tf32(v.w));
            *(uint4*)(As + row * 132 + j) = st;
        }
        __syncthreads();

        float acc[8][4] = {};
        #pragma unroll
        for (int ks = 0; ks < 16; ++ks) {
            uint4 a = ldsm4(alane + (ks << 5));
            #pragma unroll
            for (int p = 0; p < 4; ++p) {
                uint4 b = *(const uint4*)(Wf + ((h * 16 + ks) * 4 + p) * 132 + lane * 4);
                mma8(acc[2 * p],     a, b.x, b.y);
                mma8(acc[2 * p + 1], a, b.z, b.w);
            }
        }
        __syncthreads();

        int r0 = base + q * 16 + g;
        #pragma unroll
        for (int nt = 0; nt < 8; ++nt) {
            int col = h * 64 + 8 * nt + 2 * tg;
            float2 rv0 = make_float2(0.f, 0.f), rv1 = make_float2(0.f, 0.f);
            if (r0 < n) {
                float2 hv = *(const float2*)(g_h + (size_t)r0 * HH + col);
                rv0.x = hv.x + 1.f / (1.f + expf(-(acc[nt][0] + bv[2 * nt])));
                rv0.y = hv.y + 1.f / (1.f + expf(-(acc[nt][1] + bv[2 * nt + 1])));
            }
            if (r0 + 8 < n) {
                float2 hv = *(const float2*)(g_h + (size_t)(r0 + 8) * HH + col);
                rv1.x = hv.x + 1.f / (1.f + expf(-(acc[nt][2] + bv[2 * nt])));
                rv1.y = hv.y + 1.f / (1.f + expf(-(acc[nt][3] + bv[2 * nt + 1])));
            }
            *(float2*)(As + (q * 16 + g) * 132 + col)     = rv0;
            *(float2*)(As + (q * 16 + g + 8) * 132 + col) = rv1;
        }
        __syncthreads();

        for (int wi = tid; wi < 2048; wi += NT) {
            int row = wi >> 5, j = (wi & 31) << 2;
            if (base + row < n) {
                float4 v = *(const float4*)(As + row * 132 + j);
                *(float4*)(g_r + (size_t)(base + row) * HH + j) = v;
            }
        }
        {
            int c = tid & 127, half = tid >> 7;
            float s = 0.f, s2 = 0.f;
            #pragma unroll 8
            for (int r = half * 32; r < half * 32 + 32; ++r) {
                float v = As[r * 132 + c];
                s += v; s2 += v * v;
            }
            atomicAdd(&g_sum[l * HH + c], s);
            atomicAdd(&g_sq[l * HH + c],  s2);
        }
    }
}

// ---------------- final MLP with fused BN(layer 2) ----------------------------
__global__ __launch_bounds__(NT) void k_final(
    const float* __restrict__ Wf, const float* __restrict__ bf,
    const float* __restrict__ Wo, const float* __restrict__ bo,
    const float* __restrict__ gamma, const float* __restrict__ beta,
    int bnl, float* __restrict__ out, int n)
{
    extern __shared__ float smem[];
    float* As = smem;
    float* Ws = As + 64 * 132;
    float* sc = Ws + 2048;
    float* sh = sc + 128;
    const int tid = threadIdx.x;
    const int base = blockIdx.x * 64;

    if (tid < 128) {
        float invn = 1.f / (float)n;
        float mu  = g_sum[bnl * HH + tid] * invn;
        float var = g_sq[bnl * HH + tid] * invn - mu * mu;
        float s = gamma[tid] * rsqrtf(var + EPSBN);
        sc[tid] = s; sh[tid] = beta[tid] - mu * s;
    }
    __syncthreads();

    for (int t = tid; t < 64 * 32; t += NT) {
        int row = t >> 5, j = (t & 31) << 2;
        float4 v = make_float4(0.f, 0.f, 0.f, 0.f);
        if (base + row < n) {
            v = *(const float4*)(g_r + (size_t)(base + row) * HH + j);
            v.x = v.x * sc[j + 0] + sh[j + 0];
            v.y = v.y * sc[j + 1] + sh[j + 1];
            v.z = v.z * sc[j + 2] + sh[j + 2];
            v.w = v.w * sc[j + 3] + sh[j + 3];
        }
        *(float4*)(As + row * 132 + j) = v;
    }

    float acc[4][8] = {};
    gemm_acc<4>(As, 132, Ws, Wf, HH, acc, tid);

    const int ty = tid >> 4, tx = tid & 15, c0 = tx * 8;
    #pragma unroll
    for (int i = 0; i < 4; ++i)
        #pragma unroll
        for (int j = 0; j < 8; ++j)
            As[(ty * 4 + i) * 132 + c0 + j] = fmaxf(acc[i][j] + bf[c0 + j], 0.f);
    __syncthreads();

    const int w = tid >> 5, lane = tid & 31;
    #pragma unroll
    for (int rr = 0; rr < 8; ++rr) {
        int row = w * 8 + rr;
        float sAcc = 0.f;
        #pragma unroll
        for (int qq = 0; qq < 4; ++qq)
            sAcc += As[row * 132 + lane + 32 * qq] * Wo[lane + 32 * qq];
        #pragma unroll
        for (int off = 16; off; off >>= 1)
            sAcc += __shfl_xor_sync(0xffffffffu, sAcc, off);
        if (lane == 0 && base + row < n)
            out[base + row] = 1.f / (1.f + expf(-sAcc));
    }
}

// ---------------- launcher -----------------------------------------------------
extern "C" void kernel_launch(void* const* d_in, const int* in_sizes, int n_in,
                              void* d_out, int out_size)
{
    const float* x    = (const float*)d_in[0];
    const float* ea   = (const float*)d_in[1];
    const int*   ei   = (const int*)  d_in[2];
    const float* W0   = (const float*)d_in[4];
    const float* b0   = (const float*)d_in[5];
    const float* W1   = (const float*)d_in[6];
    const float* b1   = (const float*)d_in[7];
    const float* W1a  = (const float*)d_in[8];
    const float* b1a  = (const float*)d_in[9];
    const float* W1b  = (const float*)d_in[10];
    const float* b1b  = (const float*)d_in[11];
    const float* W2a  = (const float*)d_in[12];
    const float* b2a  = (const float*)d_in[13];
    const float* W2b  = (const float*)d_in[14];
    const float* b2b  = (const float*)d_in[15];
    const float* gam  = (const float*)d_in[16];
    const float* bet  = (const float*)d_in[17];
    const float* Wf   = (const float*)d_in[18];
    const float* bf   = (const float*)d_in[19];
    const float* Wo   = (const float*)d_in[20];
    const float* bo   = (const float*)d_in[21];
    float* out = (float*)d_out;

    const int n = in_sizes[0] / 2;
    const int E = in_sizes[2] / 2;
    const int* srcp = ei;
    const int* dstp = ei + E;

    const int nb_n     = (n + 63) / 64;
    const int ntiles_n = nb_n;
    const int ntiles_e = (E + 63) / 64;
    const int gPers2   = 296;
    const int gPers3   = 444;

    const size_t SM_IN = (size_t)(64 * 132 + 2048 + 256 + 128 + 128) * 4;
    const size_t SM_P  = (size_t)(8448 + 4352 + 288) * 4;                   // 52352
    const size_t SM_E  = (size_t)(8448 + 4352 + 4224 + 432 + 384) * 4;      // 71360
    const size_t SM_U1 = (size_t)(16896 + 8448 + 64) * 4;                   // 101632
    const size_t SM_U2 = (size_t)(128 * 132 + 64 * 132) * 4;                // 101376
    const size_t SM_F  = (size_t)(64 * 132 + 2048 + 256) * 4;

    cudaFuncSetAttribute(k_edge, cudaFuncAttributeMaxDynamicSharedMemorySize, (int)SM_E);
    cudaFuncSetAttribute(k_precompute, cudaFuncAttributeMaxDynamicSharedMemorySize, (int)SM_P);
    cudaFuncSetAttribute(k_update1, cudaFuncAttributeMaxDynamicSharedMemorySize, (int)SM_U1);
    cudaFuncSetAttribute(k_update2, cudaFuncAttributeMaxDynamicSharedMemorySize, (int)SM_U2);

    k_zero<<<1024, 256>>>(n);
    k_input<<<nb_n, NT, SM_IN>>>(x, W0, b0, W1, b1, dstp, E, n);
    k_scan<<<1, 1024>>>(n);
    k_sort<<<(E + 255) / 256, 256>>>(srcp, dstp, ea, E);

    for (int l = 0; l < LL; ++l) {
        const float* W1a_l  = W1a + (size_t)l * 130 * 128;
        const float* W1a_t  = W1a_l + 128 * 128;
        const float* b1a_l  = b1a + (size_t)l * 128;
        const float* W1b_l  = W1b + (size_t)l * 128 * 128;
        const float* b1b_l  = b1b + (size_t)l * 128;
        const float* W2a_l  = W2a + (size_t)l * 256 * 128;
        const float* b2a_l  = b2a + (size_t)l * 128;
        const float* W2b_l  = W2b + (size_t)l * 128 * 128;
        const float* b2b_l  = b2b + (size_t)l * 128;
        const float* gam_p  = (l > 0) ? gam + (size_t)(l - 1) * 128 : gam;
        const float* bet_p  = (l > 0) ? bet + (size_t)(l - 1) * 128 : bet;

        k_precompute<<<gPers3, NT, SM_P>>>(W1a_l, gam_p, bet_p, l - 1, n, ntiles_n);
        k_edge<<<gPers3, NT, SM_E>>>(W1a_t, b1a_l, W1b_l, b1b_l, E, ntiles_e);
        k_update1<<<gPers2, NT, SM_U1>>>(W2a_l, b2a_l, n, ntiles_n,
                                         (l < LL - 1) ? 1 : 0);
        k_update2<<<gPers2, NT, SM_U2>>>(W2b_l, b2b_l, l, n, ntiles_n);
    }

    k_final<<<nb_n, NT, SM_F>>>(Wf, bf, Wo, bo,
                                gam + (size_t)(LL - 1) * 128,
                                bet + (size_t)(LL - 1) * 128,
                                LL - 1, out, n);
}

// round 8
// speedup vs baseline: 1.6150x; 1.0861x over previous
#include <cuda_runtime.h>
#include <cuda_bf16.h>
#include <math.h>
#include <stdint.h>

#define NN 50000
#define EE 800000
#define HH 128
#define LL 3
#define NT 256
#define EPSBN 1e-5f

// ---------------- scratch ---------------------------------------------------
__device__ float    g_h[NN * HH];
__device__ unsigned g_pb[NN * 64];     // P in bf16x2
__device__ float    g_agg[NN * HH];
__device__ unsigned g_ub[NN * 64];     // U in bf16x2
__device__ float    g_r[NN * HH];
__device__ int      g_cnt[NN];
__device__ int      g_fill[NN];
__device__ int      g_eoff[NN + 1];
__device__ int      g_esrc[EE];
__device__ int      g_edst[EE];
__device__ float2   g_eea[EE];
__device__ float    g_sum[LL * HH];
__device__ float    g_sq[LL * HH];

// ---------------- mma / ldmatrix helpers -------------------------------------
__device__ __forceinline__ void mma16(float acc[4], const uint4& a,
                                      unsigned b0, unsigned b1) {
    asm volatile(
        "mma.sync.aligned.m16n8k16.row.col.f32.bf16.bf16.f32 "
        "{%0,%1,%2,%3},{%4,%5,%6,%7},{%8,%9},{%0,%1,%2,%3};\n"
        : "+f"(acc[0]), "+f"(acc[1]), "+f"(acc[2]), "+f"(acc[3])
        : "r"(a.x), "r"(a.y), "r"(a.z), "r"(a.w), "r"(b0), "r"(b1));
}
__device__ __forceinline__ uint4 ldsm4(unsigned addr) {
    uint4 r;
    asm volatile("ldmatrix.sync.aligned.m8n8.x4.shared.b16 {%0,%1,%2,%3}, [%4];"
        : "=r"(r.x), "=r"(r.y), "=r"(r.z), "=r"(r.w) : "r"(addr));
    return r;
}
// bf16 row-major A tile, stride in BYTES
__device__ __forceinline__ unsigned a_lane_addr_bf(const void* As, int strideB,
                                                   int q, int lane) {
    return (unsigned)__cvta_generic_to_shared(As)
         + (q * 16 + (lane & 7) + 8 * ((lane >> 3) & 1)) * strideB
         + (lane >> 4) * 16;
}

// KxN(128) fp32 weight -> bf16 B fragments (k16 steps)
__device__ __forceinline__ void stage_w_bf16(unsigned* Wf, const float* __restrict__ Wg,
                                             int KS, int tid)
{
    const int total = 2 * KS * 4 * 132;
    for (int i = tid; i < total; i += NT) {
        int grp = i / 132, off = i % 132;
        if (off < 128) {
            int s = off & 3, lane = off >> 2;
            int g = lane >> 2, t = lane & 3;
            int hh = grp / (KS * 4);
            int rem = grp - hh * (KS * 4);
            int ks = rem >> 2, pp = rem & 3;
            int p = 2 * pp + (s >> 1);
            int bsel = s & 1;
            int n = hh * 64 + p * 8 + g;
            int k0 = ks * 16 + 2 * t + 8 * bsel;
            __nv_bfloat162 v = __floats2bfloat162_rn(Wg[(size_t)k0 * 128 + n],
                                                     Wg[(size_t)(k0 + 1) * 128 + n]);
            Wf[i] = *(unsigned*)&v;
        }
    }
}

// ---------------- streamed-W fp32 GEMM core (k_input / k_final) -------------
template<int RPT>
__device__ __forceinline__ void gemm_acc(const float* As, int lda, float* Ws,
                                         const float* __restrict__ Wg, int K,
                                         float acc[RPT][8], int tid)
{
    const int ty = tid >> 4, tx = tid & 15;
    for (int kc = 0; kc < K; kc += 16) {
        __syncthreads();
        for (int t = tid; t < 512; t += NT) {
            int kk = t >> 5, j4 = (t & 31) << 2;
            *(float4*)(Ws + kk * HH + j4) =
                *(const float4*)(Wg + (size_t)(kc + kk) * HH + j4);
        }
        __syncthreads();
        #pragma unroll
        for (int k = 0; k < 16; ++k) {
            float a[RPT];
            #pragma unroll
            for (int i = 0; i < RPT; ++i) a[i] = As[(ty * RPT + i) * lda + kc + k];
            float4 b0 = *(const float4*)(Ws + k * HH + tx * 8);
            float4 b1 = *(const float4*)(Ws + k * HH + tx * 8 + 4);
            float bb[8] = {b0.x, b0.y, b0.z, b0.w, b1.x, b1.y, b1.z, b1.w};
            #pragma unroll
            for (int i = 0; i < RPT; ++i)
                #pragma unroll
                for (int j = 0; j < 8; ++j)
                    acc[i][j] = fmaf(a[i], bb[j], acc[i][j]);
        }
    }
    __syncthreads();
}

// ---------------- zero init --------------------------------------------------
__global__ void k_zero(int n)
{
    int total = n * HH;
    for (int i = blockIdx.x * blockDim.x + threadIdx.x; i < total;
         i += gridDim.x * blockDim.x) {
        g_agg[i] = 0.f;
        if (i < n) { g_cnt[i] = 0; g_fill[i] = 0; }
        if (i < LL * HH) { g_sum[i] = 0.f; g_sq[i] = 0.f; }
    }
}

// ---------------- single-block scan -> exclusive offsets ---------------------
__global__ void k_scan(int n)
{
    __shared__ int buf[1024];
    __shared__ int carrys;
    int tid = threadIdx.x;
    if (tid == 0) carrys = 0;
    __syncthreads();
    for (int base = 0; base < n; base += 1024) {
        int v = (base + tid < n) ? g_cnt[base + tid] : 0;
        buf[tid] = v;
        __syncthreads();
        for (int off = 1; off < 1024; off <<= 1) {
            int t = (tid >= off) ? buf[tid - off] : 0;
            __syncthreads();
            buf[tid] += t;
            __syncthreads();
        }
        if (base + tid < n) g_eoff[base + tid] = carrys + buf[tid] - v;
        int tot = buf[1023];
        __syncthreads();
        if (tid == 0) carrys += tot;
        __syncthreads();
    }
    if (tid == 0) g_eoff[n] = carrys;
}

// ---------------- counting-sort scatter --------------------------------------
__global__ void k_sort(const int* __restrict__ src, const int* __restrict__ dst,
                       const float* __restrict__ ea, int E)
{
    int e = blockIdx.x * blockDim.x + threadIdx.x;
    if (e < E) {
        int d = dst[e];
        int slot = g_eoff[d] + atomicAdd(&g_fill[d], 1);
        g_esrc[slot] = src[e];
        g_edst[slot] = d;
        g_eea[slot] = make_float2(ea[2 * e], ea[2 * e + 1]);
    }
}

// ---------------- input MLP + degree count -----------------------------------
__global__ __launch_bounds__(NT) void k_input(
    const float* __restrict__ x,
    const float* __restrict__ W0, const float* __restrict__ b0,
    const float* __restrict__ W1, const float* __restrict__ b1,
    const int* __restrict__ dst, int E, int n)
{
    extern __shared__ float smem[];
    float* As  = smem;
    float* Ws  = As + 64 * 132;
    float* w0s = Ws + 2048;
    float* b0s = w0s + 256;
    float* xs  = b0s + 128;
    const int tid = threadIdx.x;
    const int base = blockIdx.x * 64;

    for (int e = blockIdx.x * blockDim.x + tid; e < E; e += gridDim.x * blockDim.x)
        atomicAdd(&g_cnt[dst[e]], 1);

    for (int t = tid; t < 256; t += NT) w0s[t] = W0[t];
    for (int t = tid; t < 128; t += NT) b0s[t] = b0[t];
    if (tid < 128) {
        int row = tid >> 1;
        xs[tid] = (base + row < n) ? x[(size_t)(base + row) * 2 + (tid & 1)] : 0.f;
    }
    __syncthreads();

    for (int t = tid; t < 64 * 32; t += NT) {
        int row = t >> 5, j = (t & 31) << 2;
        float x0 = xs[row * 2], x1 = xs[row * 2 + 1];
        float4 v;
        v.x = fmaxf(fmaf(x0, w0s[j + 0], fmaf(x1, w0s[128 + j + 0], b0s[j + 0])), 0.f);
        v.y = fmaxf(fmaf(x0, w0s[j + 1], fmaf(x1, w0s[128 + j + 1], b0s[j + 1])), 0.f);
        v.z = fmaxf(fmaf(x0, w0s[j + 2], fmaf(x1, w0s[128 + j + 2], b0s[j + 2])), 0.f);
        v.w = fmaxf(fmaf(x0, w0s[j + 3], fmaf(x1, w0s[128 + j + 3], b0s[j + 3])), 0.f);
        *(float4*)(As + row * 132 + j) = v;
    }

    float acc[4][8] = {};
    gemm_acc<4>(As, 132, Ws, W1, HH, acc, tid);

    const int ty = tid >> 4, tx = tid & 15, c0 = tx * 8;
    #pragma unroll
    for (int i = 0; i < 4; ++i) {
        int row = base + ty * 4 + i;
        if (row < n) {
            #pragma unroll
            for (int j = 0; j < 8; ++j)
                g_h[(size_t)row * HH + c0 + j] = fmaxf(acc[i][j] + b1[c0 + j], 0.f);
        }
    }
}

// ---------------- P = BN?(h) @ W1a_top : bf16 mma, fused BN -------------------
__global__ void __launch_bounds__(NT, 3) k_precompute(
    const float* __restrict__ W,
    const float* __restrict__ gamma, const float* __restrict__ beta,
    int bnl, int n, int ntiles)
{
    extern __shared__ float smem[];
    unsigned* Wf = (unsigned*)smem;                      // 8448 words
    __nv_bfloat16* As = (__nv_bfloat16*)(Wf + 8448);     // 64 x 136 bf16
    float* scp = (float*)(As + 64 * 136);                // 144
    float* shp = scp + 144;                              // 144
    const int tid  = threadIdx.x;
    const int lane = tid & 31, w = tid >> 5;
    const int q = w & 3, h = w >> 2;
    const int g2 = lane >> 2, tg = lane & 3;

    stage_w_bf16(Wf, W, 8, tid);
    if (tid < 128) {
        int c = tid >> 3, s = tid & 7;
        if (bnl >= 0) {
            float invn = 1.f / (float)n;
            float mu  = g_sum[bnl * HH + tid] * invn;
            float var = g_sq[bnl * HH + tid] * invn - mu * mu;
            float sv = gamma[tid] * rsqrtf(var + EPSBN);
            scp[c * 9 + s] = sv; shp[c * 9 + s] = beta[tid] - mu * sv;
        } else { scp[c * 9 + s] = 1.f; shp[c * 9 + s] = 0.f; }
    }
    const unsigned alane = a_lane_addr_bf(As, 272, q, lane);
    const int pc = tid & 15;

    for (int tile = blockIdx.x; tile < ntiles; tile += gridDim.x) {
        const int base = tile * 64;
        __syncthreads();
        for (int wi = tid; wi < 1024; wi += NT) {
            int row = wi >> 4, j = pc * 8;
            int node = base + row;
            float v[8] = {0,0,0,0,0,0,0,0};
            if (node < n) {
                float4 va, vb;
                if (bnl >= 0) {
                    va = *(const float4*)(g_r + (size_t)node * HH + j);
                    vb = *(const float4*)(g_r + (size_t)node * HH + j + 4);
                    float vv[8] = {va.x,va.y,va.z,va.w,vb.x,vb.y,vb.z,vb.w};
                    #pragma unroll
                    for (int s = 0; s < 8; ++s)
                        v[s] = vv[s] * scp[pc * 9 + s] + shp[pc * 9 + s];
                    *(float4*)(g_h + (size_t)node * HH + j)     = make_float4(v[0],v[1],v[2],v[3]);
                    *(float4*)(g_h + (size_t)node * HH + j + 4) = make_float4(v[4],v[5],v[6],v[7]);
                } else {
                    va = *(const float4*)(g_h + (size_t)node * HH + j);
                    vb = *(const float4*)(g_h + (size_t)node * HH + j + 4);
                    v[0]=va.x; v[1]=va.y; v[2]=va.z; v[3]=va.w;
                    v[4]=vb.x; v[5]=vb.y; v[6]=vb.z; v[7]=vb.w;
                }
            }
            unsigned outw[4];
            #pragma unroll
            for (int s = 0; s < 4; ++s) {
                __nv_bfloat162 mb = __floats2bfloat162_rn(v[2*s], v[2*s+1]);
                outw[s] = *(unsigned*)&mb;
            }
            *(uint4*)(As + row * 136 + j) = *(uint4*)outw;
        }
        __syncthreads();

        float acc[8][4] = {};
        #pragma unroll
        for (int ks = 0; ks < 8; ++ks) {
            uint4 a = ldsm4(alane + ks * 32);
            #pragma unroll
            for (int pp = 0; pp < 4; ++pp) {
                uint4 b = *(const uint4*)(Wf + ((h * 8 + ks) * 4 + pp) * 132 + lane * 4);
                mma16(acc[2 * pp],     a, b.x, b.y);
                mma16(acc[2 * pp + 1], a, b.z, b.w);
            }
        }
        int r0 = base + q * 16 + g2;
        #pragma unroll
        for (int nt = 0; nt < 8; ++nt) {
            int col = h * 64 + 8 * nt + 2 * tg;
            if (r0 < n) {
                __nv_bfloat162 pv = __floats2bfloat162_rn(acc[nt][0], acc[nt][1]);
                g_pb[(size_t)r0 * 64 + (col >> 1)] = *(unsigned*)&pv;
            }
            if (r0 + 8 < n) {
                __nv_bfloat162 pv = __floats2bfloat162_rn(acc[nt][2], acc[nt][3]);
                g_pb[(size_t)(r0 + 8) * 64 + (col >> 1)] = *(unsigned*)&pv;
            }
        }
    }
}

// ---------------- edge kernel: Ds overlaid on As, 4 blocks/SM -----------------
__global__ void __launch_bounds__(NT, 4) k_edge(
    const float* __restrict__ Wtail,
    const float* __restrict__ b1a,
    const float* __restrict__ W1b, const float* __restrict__ b1b,
    int E, int ntiles)
{
    extern __shared__ float smem[];
    unsigned* Wf = (unsigned*)smem;                      // 8448 words
    __nv_bfloat16* As = (__nv_bfloat16*)(Wf + 8448);     // 64 x 136 bf16 (4352 w)
    float* Ds  = (float*)As;                             // overlays As (4224 w)
    float* wt0p = (float*)(Wf + 8448 + 4352);            // 144
    float* wt1p = wt0p + 144;                            // 144
    float* bsp  = wt1p + 144;                            // 144
    float* b2s  = bsp + 144;                             // 128
    float* eas  = b2s + 128;                             // 128
    int*   sd   = (int*)(eas + 128);                     // 128

    const int tid  = threadIdx.x;
    const int lane = tid & 31, w = tid >> 5;
    const int q = w & 3, h = w >> 2;
    const int g2 = lane >> 2, tg = lane & 3;

    stage_w_bf16(Wf, W1b, 8, tid);
    if (tid < 128) {
        int c = tid >> 3, s = tid & 7;
        wt0p[c * 9 + s] = Wtail[tid];
        wt1p[c * 9 + s] = Wtail[128 + tid];
        bsp[c * 9 + s]  = b1a[tid];
        b2s[tid] = b1b[tid];
    }
    const unsigned alane = a_lane_addr_bf(As, 272, q, lane);
    const int pc = tid & 15;
    const int pairc = tid & 63, rg = tid >> 6;

    for (int tile = blockIdx.x; tile < ntiles; tile += gridDim.x) {
        const int e0 = tile * 64;
        __syncthreads();
        if (tid < 64) {
            int e = e0 + tid;
            if (e < E) {
                sd[tid]      = g_esrc[e];
                sd[64 + tid] = g_edst[e];
                float2 ee = g_eea[e];
                eas[2 * tid] = ee.x; eas[2 * tid + 1] = ee.y;
            } else {
                sd[tid] = 0; sd[64 + tid] = -1;
                eas[2 * tid] = 0.f; eas[2 * tid + 1] = 0.f;
            }
        }
        __syncthreads();

        for (int wi = tid; wi < 1024; wi += NT) {
            int row = wi >> 4, j = pc * 8;
            uint4 p8 = ((const uint4*)(g_pb + (size_t)sd[row] * 64))[pc];
            float ev0 = eas[2 * row], ev1 = eas[2 * row + 1];
            unsigned pw[4] = {p8.x, p8.y, p8.z, p8.w};
            unsigned outw[4];
            #pragma unroll
            for (int s = 0; s < 4; ++s) {
                float2 pf = __bfloat1622float2(*(__nv_bfloat162*)&pw[s]);
                float m0 = fmaf(ev0, wt0p[pc*9 + 2*s],
                                fmaf(ev1, wt1p[pc*9 + 2*s],   pf.x + bsp[pc*9 + 2*s]));
                float m1 = fmaf(ev0, wt0p[pc*9 + 2*s+1],
                                fmaf(ev1, wt1p[pc*9 + 2*s+1], pf.y + bsp[pc*9 + 2*s+1]));
                __nv_bfloat162 mb = __floats2bfloat162_rn(fmaxf(m0, 0.f), fmaxf(m1, 0.f));
                outw[s] = *(unsigned*)&mb;
            }
            *(uint4*)(As + row * 136 + j) = *(uint4*)outw;
        }
        __syncthreads();

        float acc[8][4] = {};
        #pragma unroll
        for (int ks = 0; ks < 8; ++ks) {
            uint4 a = ldsm4(alane + ks * 32);
            #pragma unroll
            for (int pp = 0; pp < 4; ++pp) {
                uint4 b = *(const uint4*)(Wf + ((h * 8 + ks) * 4 + pp) * 132 + lane * 4);
                mma16(acc[2 * pp],     a, b.x, b.y);
                mma16(acc[2 * pp + 1], a, b.z, b.w);
            }
        }

        // two-phase epilogue: D staged into Ds (overlaid on As) -> segmented red
        #pragma unroll
        for (int p = 0; p < 2; ++p) {
            __syncthreads();                 // all mma/ldsm (and prior reduce) done
            if ((q >> 1) == p) {
                int lr = (q & 1) * 16 + g2;
                #pragma unroll
                for (int nt = 0; nt < 8; ++nt) {
                    int col = h * 64 + 8 * nt + 2 * tg;
                    float bb0 = b2s[col], bb1 = b2s[col + 1];
                    *(float2*)(Ds + lr * 132 + col) =
                        make_float2(fmaxf(acc[nt][0] + bb0, 0.f),
                                    fmaxf(acc[nt][1] + bb1, 0.f));
                    *(float2*)(Ds + (lr + 8) * 132 + col) =
                        make_float2(fmaxf(acc[nt][2] + bb0, 0.f),
                                    fmaxf(acc[nt][3] + bb1, 0.f));
                }
            }
            __syncthreads();
            int gr = p * 32 + rg * 8;
            float2 sv = make_float2(0.f, 0.f);
            int cur = sd[64 + gr];
            #pragma unroll
            for (int r = 0; r < 8; ++r) {
                int dd = sd[64 + gr + r];
                float2 v = *(const float2*)(Ds + (rg * 8 + r) * 132 + pairc * 2);
                if (dd != cur) {
                    if (cur >= 0)
                        asm volatile("red.global.add.v2.f32 [%0], {%1,%2};"
                                     :: "l"(g_agg + (size_t)cur * HH + pairc * 2),
                                        "f"(sv.x), "f"(sv.y) : "memory");
                    sv = make_float2(0.f, 0.f);
                    cur = dd;
                }
                sv.x += v.x; sv.y += v.y;
            }
            if (cur >= 0)
                asm volatile("red.global.add.v2.f32 [%0], {%1,%2};"
                             :: "l"(g_agg + (size_t)cur * HH + pairc * 2),
                                "f"(sv.x), "f"(sv.y) : "memory");
        }
    }
}

// ---------------- update1: U = relu([h | agg/deg] @ W2a + b2a) -> g_ub -------
__global__ void __launch_bounds__(NT, 2) k_update1(
    const float* __restrict__ W2a, const float* __restrict__ b2a,
    int n, int ntiles, int zero_agg)
{
    extern __shared__ float smem[];
    unsigned* Wf = (unsigned*)smem;                      // 16896 words
    __nv_bfloat16* As = (__nv_bfloat16*)(Wf + 16896);    // 64 x 264 bf16 (8448 w)
    float* sinv = (float*)(As + 64 * 264);               // 64
    const int tid  = threadIdx.x;
    const int lane = tid & 31, w = tid >> 5;
    const int q = w & 3, h = w >> 2;
    const int g = lane >> 2, tg = lane & 3;

    stage_w_bf16(Wf, W2a, 16, tid);
    float bv[16];
    #pragma unroll
    for (int nt = 0; nt < 8; ++nt) {
        int col = h * 64 + 8 * nt + 2 * tg;
        bv[2 * nt]     = b2a[col];
        bv[2 * nt + 1] = b2a[col + 1];
    }
    const unsigned alane = a_lane_addr_bf(As, 528, q, lane);
    const int cu = tid & 31;

    for (int tile = blockIdx.x; tile < ntiles; tile += gridDim.x) {
        const int base = tile * 64;
        __syncthreads();
        if (tid < 64) {
            int node = base + tid;
            sinv[tid] = (node < n) ? 1.f / fmaxf((float)g_cnt[node], 1.f) : 0.f;
        }
        __syncthreads();

        for (int wi = tid; wi < 2048; wi += NT) {
            int row = wi >> 5, j = cu * 8;
            int node = base + row;
            float v[8] = {0,0,0,0,0,0,0,0};
            if (node < n) {
                if (cu < 16) {
                    float4 va = *(const float4*)(g_h + (size_t)node * HH + j);
                    float4 vb = *(const float4*)(g_h + (size_t)node * HH + j + 4);
                    v[0]=va.x; v[1]=va.y; v[2]=va.z; v[3]=va.w;
                    v[4]=vb.x; v[5]=vb.y; v[6]=vb.z; v[7]=vb.w;
                } else {
                    int ja = j - 128;
                    float4 va = *(const float4*)(g_agg + (size_t)node * HH + ja);
                    float4 vb = *(const float4*)(g_agg + (size_t)node * HH + ja + 4);
                    float iv = sinv[row];
                    v[0]=va.x*iv; v[1]=va.y*iv; v[2]=va.z*iv; v[3]=va.w*iv;
                    v[4]=vb.x*iv; v[5]=vb.y*iv; v[6]=vb.z*iv; v[7]=vb.w*iv;
                    if (zero_agg) {
                        *(float4*)(g_agg + (size_t)node * HH + ja)     = make_float4(0,0,0,0);
                        *(float4*)(g_agg + (size_t)node * HH + ja + 4) = make_float4(0,0,0,0);
                    }
                }
            }
            unsigned outw[4];
            #pragma unroll
            for (int s = 0; s < 4; ++s) {
                __nv_bfloat162 mb = __floats2bfloat162_rn(v[2*s], v[2*s+1]);
                outw[s] = *(unsigned*)&mb;
            }
            *(uint4*)(As + row * 264 + j) = *(uint4*)outw;
        }
        __syncthreads();

        float acc[8][4] = {};
        #pragma unroll
        for (int ks = 0; ks < 16; ++ks) {
            uint4 a = ldsm4(alane + ks * 32);
            #pragma unroll
            for (int pp = 0; pp < 4; ++pp) {
                uint4 b = *(const uint4*)(Wf + ((h * 16 + ks) * 4 + pp) * 132 + lane * 4);
                mma16(acc[2 * pp],     a, b.x, b.y);
                mma16(acc[2 * pp + 1], a, b.z, b.w);
            }
        }

        int r0 = base + q * 16 + g;
        #pragma unroll
        for (int nt = 0; nt < 8; ++nt) {
            int col = h * 64 + 8 * nt + 2 * tg;
            if (r0 < n) {
                __nv_bfloat162 uv = __floats2bfloat162_rn(
                    fmaxf(acc[nt][0] + bv[2 * nt], 0.f),
                    fmaxf(acc[nt][1] + bv[2 * nt + 1], 0.f));
                g_ub[(size_t)r0 * 64 + (col >> 1)] = *(unsigned*)&uv;
            }
            if (r0 + 8 < n) {
                __nv_bfloat162 uv = __floats2bfloat162_rn(
                    fmaxf(acc[nt][2] + bv[2 * nt], 0.f),
                    fmaxf(acc[nt][3] + bv[2 * nt + 1], 0.f));
                g_ub[(size_t)(r0 + 8) * 64 + (col >> 1)] = *(unsigned*)&uv;
            }
        }
    }
}

// ---------------- update2: out=sigmoid(U@W2b+b), r=h+out, BN stats (bf16) ----
__global__ void __launch_bounds__(NT, 3) k_update2(
    const float* __restrict__ W2b, const float* __restrict__ b2b,
    int l, int n, int ntiles)
{
    extern __shared__ float smem[];
    unsigned* Wf = (unsigned*)smem;                      // 8448 words
    // union region (8448 w): As (bf16 64x136, first 4352 w) then Dr (f32 64x132)
    __nv_bfloat16* As = (__nv_bfloat16*)(Wf + 8448);
    float* Dr = (float*)(Wf + 8448);
    const int tid  = threadIdx.x;
    const int lane = tid & 31, w = tid >> 5;
    const int q = w & 3, h = w >> 2;
    const int g = lane >> 2, tg = lane & 3;

    stage_w_bf16(Wf, W2b, 8, tid);
    float bv[16];
    #pragma unroll
    for (int nt = 0; nt < 8; ++nt) {
        int col = h * 64 + 8 * nt + 2 * tg;
        bv[2 * nt]     = b2b[col];
        bv[2 * nt + 1] = b2b[col + 1];
    }
    const unsigned alane = a_lane_addr_bf(As, 272, q, lane);
    const int pc = tid & 15;

    for (int tile = blockIdx.x; tile < ntiles; tile += gridDim.x) {
        const int base = tile * 64;
        __syncthreads();
        // producer: pure bf16 copy from g_ub
        for (int wi = tid; wi < 1024; wi += NT) {
            int row = wi >> 4;
            int node = base + row;
            uint4 u = make_uint4(0, 0, 0, 0);
            if (node < n) u = ((const uint4*)(g_ub + (size_t)node * 64))[pc];
            *(uint4*)(As + row * 136 + pc * 8) = u;
        }
        __syncthreads();

        float acc[8][4] = {};
        #pragma unroll
        for (int ks = 0; ks < 8; ++ks) {
            uint4 a = ldsm4(alane + ks * 32);
            #pragma unroll
            for (int pp = 0; pp < 4; ++pp) {
                uint4 b = *(const uint4*)(Wf + ((h * 8 + ks) * 4 + pp) * 132 + lane * 4);
                mma16(acc[2 * pp],     a, b.x, b.y);
                mma16(acc[2 * pp + 1], a, b.z, b.w);
            }
        }
        __syncthreads();   // ldsm reads done -> Dr may overwrite As region

        int r0 = base + q * 16 + g;
        #pragma unroll
        for (int nt = 0; nt < 8; ++nt) {
            int col = h * 64 + 8 * nt + 2 * tg;
            float2 rv0 = make_float2(0.f, 0.f), rv1 = make_float2(0.f, 0.f);
            if (r0 < n) {
                float2 hv = *(const float2*)(g_h + (size_t)r0 * HH + col);
                rv0.x = hv.x + 1.f / (1.f + expf(-(acc[nt][0] + bv[2 * nt])));
                rv0.y = hv.y + 1.f / (1.f + expf(-(acc[nt][1] + bv[2 * nt + 1])));
            }
            if (r0 + 8 < n) {
                float2 hv = *(const float2*)(g_h + (size_t)(r0 + 8) * HH + col);
                rv1.x = hv.x + 1.f / (1.f + expf(-(acc[nt][2] + bv[2 * nt])));
                rv1.y = hv.y + 1.f / (1.f + expf(-(acc[nt][3] + bv[2 * nt + 1])));
            }
            *(float2*)(Dr + (q * 16 + g) * 132 + col)     = rv0;
            *(float2*)(Dr + (q * 16 + g + 8) * 132 + col) = rv1;
        }
        __syncthreads();

        for (int wi = tid; wi < 2048; wi += NT) {
            int row = wi >> 5, j = (wi & 31) << 2;
            if (base + row < n) {
                float4 v = *(const float4*)(Dr + row * 132 + j);
                *(float4*)(g_r + (size_t)(base + row) * HH + j) = v;
            }
        }
        {
            int c = tid & 127, half = tid >> 7;
            float s = 0.f, s2 = 0.f;
            #pragma unroll 8
            for (int r = half * 32; r < half * 32 + 32; ++r) {
                float v = Dr[r * 132 + c];
                s += v; s2 += v * v;
            }
            atomicAdd(&g_sum[l * HH + c], s);
            atomicAdd(&g_sq[l * HH + c],  s2);
        }
    }
}

// ---------------- final MLP with fused BN(layer 2) ----------------------------
__global__ __launch_bounds__(NT) void k_final(
    const float* __restrict__ Wf, const float* __restrict__ bf,
    const float* __restrict__ Wo, const float* __restrict__ bo,
    const float* __restrict__ gamma, const float* __restrict__ beta,
    int bnl, float* __restrict__ out, int n)
{
    extern __shared__ float smem[];
    float* As = smem;
    float* Ws = As + 64 * 132;
    float* sc = Ws + 2048;
    float* sh = sc + 128;
    const int tid = threadIdx.x;
    const int base = blockIdx.x * 64;

    if (tid < 128) {
        float invn = 1.f / (float)n;
        float mu  = g_sum[bnl * HH + tid] * invn;
        float var = g_sq[bnl * HH + tid] * invn - mu * mu;
        float s = gamma[tid] * rsqrtf(var + EPSBN);
        sc[tid] = s; sh[tid] = beta[tid] - mu * s;
    }
    __syncthreads();

    for (int t = tid; t < 64 * 32; t += NT) {
        int row = t >> 5, j = (t & 31) << 2;
        float4 v = make_float4(0.f, 0.f, 0.f, 0.f);
        if (base + row < n) {
            v = *(const float4*)(g_r + (size_t)(base + row) * HH + j);
            v.x = v.x * sc[j + 0] + sh[j + 0];
            v.y = v.y * sc[j + 1] + sh[j + 1];
            v.z = v.z * sc[j + 2] + sh[j + 2];
            v.w = v.w * sc[j + 3] + sh[j + 3];
        }
        *(float4*)(As + row * 132 + j) = v;
    }

    float acc[4][8] = {};
    gemm_acc<4>(As, 132, Ws, Wf, HH, acc, tid);

    const int ty = tid >> 4, tx = tid & 15, c0 = tx * 8;
    #pragma unroll
    for (int i = 0; i < 4; ++i)
        #pragma unroll
        for (int j = 0; j < 8; ++j)
            As[(ty * 4 + i) * 132 + c0 + j] = fmaxf(acc[i][j] + bf[c0 + j], 0.f);
    __syncthreads();

    const int w = tid >> 5, lane = tid & 31;
    #pragma unroll
    for (int rr = 0; rr < 8; ++rr) {
        int row = w * 8 + rr;
        float sAcc = 0.f;
        #pragma unroll
        for (int qq = 0; qq < 4; ++qq)
            sAcc += As[row * 132 + lane + 32 * qq] * Wo[lane + 32 * qq];
        #pragma unroll
        for (int off = 16; off; off >>= 1)
            sAcc += __shfl_xor_sync(0xffffffffu, sAcc, off);
        if (lane == 0 && base + row < n)
            out[base + row] = 1.f / (1.f + expf(-sAcc));
    }
}

// ---------------- launcher -----------------------------------------------------
extern "C" void kernel_launch(void* const* d_in, const int* in_sizes, int n_in,
                              void* d_out, int out_size)
{
    const float* x    = (const float*)d_in[0];
    const float* ea   = (const float*)d_in[1];
    const int*   ei   = (const int*)  d_in[2];
    const float* W0   = (const float*)d_in[4];
    const float* b0   = (const float*)d_in[5];
    const float* W1   = (const float*)d_in[6];
    const float* b1   = (const float*)d_in[7];
    const float* W1a  = (const float*)d_in[8];
    const float* b1a  = (const float*)d_in[9];
    const float* W1b  = (const float*)d_in[10];
    const float* b1b  = (const float*)d_in[11];
    const float* W2a  = (const float*)d_in[12];
    const float* b2a  = (const float*)d_in[13];
    const float* W2b  = (const float*)d_in[14];
    const float* b2b  = (const float*)d_in[15];
    const float* gam  = (const float*)d_in[16];
    const float* bet  = (const float*)d_in[17];
    const float* Wf   = (const float*)d_in[18];
    const float* bf   = (const float*)d_in[19];
    const float* Wo   = (const float*)d_in[20];
    const float* bo   = (const float*)d_in[21];
    float* out = (float*)d_out;

    const int n = in_sizes[0] / 2;
    const int E = in_sizes[2] / 2;
    const int* srcp = ei;
    const int* dstp = ei + E;

    const int nb_n     = (n + 63) / 64;
    const int ntiles_n = nb_n;
    const int ntiles_e = (E + 63) / 64;
    const int gPers2   = 296;
    const int gPers3   = 444;
    const int gPers4   = 592;

    const size_t SM_IN = (size_t)(64 * 132 + 2048 + 256 + 128 + 128) * 4;
    const size_t SM_P  = (size_t)(8448 + 4352 + 288) * 4;                   // 52352
    const size_t SM_E  = (size_t)(8448 + 4352 + 432 + 128 + 128 + 128) * 4; // 54464
    const size_t SM_U1 = (size_t)(16896 + 8448 + 64) * 4;                   // 101632
    const size_t SM_U2 = (size_t)(8448 + 8448) * 4;                         // 67584
    const size_t SM_F  = (size_t)(64 * 132 + 2048 + 256) * 4;

    cudaFuncSetAttribute(k_edge, cudaFuncAttributeMaxDynamicSharedMemorySize, (int)SM_E);
    cudaFuncSetAttribute(k_precompute, cudaFuncAttributeMaxDynamicSharedMemorySize, (int)SM_P);
    cudaFuncSetAttribute(k_update1, cudaFuncAttributeMaxDynamicSharedMemorySize, (int)SM_U1);
    cudaFuncSetAttribute(k_update2, cudaFuncAttributeMaxDynamicSharedMemorySize, (int)SM_U2);

    k_zero<<<1024, 256>>>(n);
    k_input<<<nb_n, NT, SM_IN>>>(x, W0, b0, W1, b1, dstp, E, n);
    k_scan<<<1, 1024>>>(n);
    k_sort<<<(E + 255) / 256, 256>>>(srcp, dstp, ea, E);

    for (int l = 0; l < LL; ++l) {
        const float* W1a_l  = W1a + (size_t)l * 130 * 128;
        const float* W1a_t  = W1a_l + 128 * 128;
        const float* b1a_l  = b1a + (size_t)l * 128;
        const float* W1b_l  = W1b + (size_t)l * 128 * 128;
        const float* b1b_l  = b1b + (size_t)l * 128;
        const float* W2a_l  = W2a + (size_t)l * 256 * 128;
        const float* b2a_l  = b2a + (size_t)l * 128;
        const float* W2b_l  = W2b + (size_t)l * 128 * 128;
        const float* b2b_l  = b2b + (size_t)l * 128;
        const float* gam_p  = (l > 0) ? gam + (size_t)(l - 1) * 128 : gam;
        const float* bet_p  = (l > 0) ? bet + (size_t)(l - 1) * 128 : bet;

        k_precompute<<<gPers3, NT, SM_P>>>(W1a_l, gam_p, bet_p, l - 1, n, ntiles_n);
        k_edge<<<gPers4, NT, SM_E>>>(W1a_t, b1a_l, W1b_l, b1b_l, E, ntiles_e);
        k_update1<<<gPers2, NT, SM_U1>>>(W2a_l, b2a_l, n, ntiles_n,
                                         (l < LL - 1) ? 1 : 0);
        k_update2<<<gPers3, NT, SM_U2>>>(W2b_l, b2b_l, l, n, ntiles_n);
    }

    k_final<<<nb_n, NT, SM_F>>>(Wf, bf, Wo, bo,
                                gam + (size_t)(LL - 1) * 128,
                                bet + (size_t)(LL - 1) * 128,
                                LL - 1, out, n);
}

// round 9
// speedup vs baseline: 1.7751x; 1.0991x over previous
#include <cuda_runtime.h>
#include <cuda_bf16.h>
#include <math.h>
#include <stdint.h>

#define NN 50000
#define EE 800000
#define HH 128
#define LL 3
#define NT 256
#define EPSBN 1e-5f

// ---------------- scratch ---------------------------------------------------
__device__ float    g_h[NN * HH];
__device__ unsigned g_pb[NN * 64];     // P in bf16x2
__device__ float    g_agg[NN * HH];
__device__ unsigned g_ub[NN * 64];     // U in bf16x2
__device__ float    g_r[NN * HH];
__device__ int      g_cnt[NN];
__device__ int      g_fill[NN];
__device__ int      g_eoff[NN + 1];
__device__ int      g_bsum[128];
__device__ int      g_esrc[EE];
__device__ int      g_edst[EE];
__device__ float2   g_eea[EE];
__device__ float    g_sum[LL * HH];
__device__ float    g_sq[LL * HH];

// ---------------- mma / ldmatrix helpers -------------------------------------
__device__ __forceinline__ unsigned f2tf32(float f) {
    unsigned u;
    asm("cvt.rna.tf32.f32 %0, %1;" : "=r"(u) : "f"(f));
    return u;
}
__device__ __forceinline__ void mma8(float acc[4], const uint4& a,
                                     unsigned b0, unsigned b1) {
    asm volatile(
        "mma.sync.aligned.m16n8k8.row.col.f32.tf32.tf32.f32 "
        "{%0,%1,%2,%3},{%4,%5,%6,%7},{%8,%9},{%0,%1,%2,%3};\n"
        : "+f"(acc[0]), "+f"(acc[1]), "+f"(acc[2]), "+f"(acc[3])
        : "r"(a.x), "r"(a.y), "r"(a.z), "r"(a.w), "r"(b0), "r"(b1));
}
__device__ __forceinline__ void mma16(float acc[4], const uint4& a,
                                      unsigned b0, unsigned b1) {
    asm volatile(
        "mma.sync.aligned.m16n8k16.row.col.f32.bf16.bf16.f32 "
        "{%0,%1,%2,%3},{%4,%5,%6,%7},{%8,%9},{%0,%1,%2,%3};\n"
        : "+f"(acc[0]), "+f"(acc[1]), "+f"(acc[2]), "+f"(acc[3])
        : "r"(a.x), "r"(a.y), "r"(a.z), "r"(a.w), "r"(b0), "r"(b1));
}
__device__ __forceinline__ uint4 ldsm4(unsigned addr) {
    uint4 r;
    asm volatile("ldmatrix.sync.aligned.m8n8.x4.shared.b16 {%0,%1,%2,%3}, [%4];"
        : "=r"(r.x), "=r"(r.y), "=r"(r.z), "=r"(r.w) : "r"(addr));
    return r;
}
// tf32 A-frag lane address (fp32 row-major, lda floats)
__device__ __forceinline__ unsigned a_lane_addr(const float* As, int lda,
                                                int q, int lane) {
    return (unsigned)__cvta_generic_to_shared(As)
         + ((((q * 16 + (lane & 15)) * lda) + 4 * (lane >> 4)) << 2);
}
// bf16 row-major A tile, stride in BYTES
__device__ __forceinline__ unsigned a_lane_addr_bf(const void* As, int strideB,
                                                   int q, int lane) {
    return (unsigned)__cvta_generic_to_shared(As)
         + (q * 16 + (lane & 7) + 8 * ((lane >> 3) & 1)) * strideB
         + (lane >> 4) * 16;
}

// KxN(128) fp32 weight -> tf32 B fragments (k8 steps, KS = K/8)
__device__ __forceinline__ void stage_w_frag(float* Wf, const float* __restrict__ Wg,
                                             int KS, int tid)
{
    const int total = 2 * KS * 4 * 132;
    for (int i = tid; i < total; i += NT) {
        int grp = i / 132, off = i % 132;
        if (off < 128) {
            int s = off & 3, t = off >> 2;
            int gg = t >> 2, tt = t & 3;
            int hh = grp / (KS * 4);
            int rem = grp - hh * (KS * 4);
            int ks = rem >> 2, p = rem & 3;
            int k = 8 * ks + tt + ((s & 1) ? 4 : 0);
            int n = hh * 64 + 16 * p + gg + ((s >= 2) ? 8 : 0);
            Wf[i] = __uint_as_float(f2tf32(Wg[(size_t)k * 128 + n]));
        }
    }
}
// KxN(128) fp32 weight -> bf16 B fragments (k16 steps, KS = K/16... passed as K/8/2)
__device__ __forceinline__ void stage_w_bf16(unsigned* Wf, const float* __restrict__ Wg,
                                             int KS, int tid)
{
    const int total = 2 * KS * 4 * 132;
    for (int i = tid; i < total; i += NT) {
        int grp = i / 132, off = i % 132;
        if (off < 128) {
            int s = off & 3, lane = off >> 2;
            int g = lane >> 2, t = lane & 3;
            int hh = grp / (KS * 4);
            int rem = grp - hh * (KS * 4);
            int ks = rem >> 2, pp = rem & 3;
            int p = 2 * pp + (s >> 1);
            int bsel = s & 1;
            int n = hh * 64 + p * 8 + g;
            int k0 = ks * 16 + 2 * t + 8 * bsel;
            __nv_bfloat162 v = __floats2bfloat162_rn(Wg[(size_t)k0 * 128 + n],
                                                     Wg[(size_t)(k0 + 1) * 128 + n]);
            Wf[i] = *(unsigned*)&v;
        }
    }
}

// ---------------- zero init --------------------------------------------------
__global__ void k_zero(int n)
{
    int total = n * HH;
    for (int i = blockIdx.x * blockDim.x + threadIdx.x; i < total;
         i += gridDim.x * blockDim.x) {
        g_agg[i] = 0.f;
        if (i < n) { g_cnt[i] = 0; g_fill[i] = 0; }
        if (i < LL * HH) { g_sum[i] = 0.f; g_sq[i] = 0.f; }
    }
}

// ---------------- fast two-level scan ----------------------------------------
__global__ void k_scanA(int n)
{
    __shared__ int buf[1024];
    const int tid = threadIdx.x;
    const int base = blockIdx.x * 1024;
    int v = (base + tid < n) ? g_cnt[base + tid] : 0;
    buf[tid] = v;
    __syncthreads();
    for (int off = 1; off < 1024; off <<= 1) {
        int t = (tid >= off) ? buf[tid - off] : 0;
        __syncthreads();
        buf[tid] += t;
        __syncthreads();
    }
    if (base + tid < n) g_eoff[base + tid] = buf[tid];   // inclusive for now
    if (tid == 1023) g_bsum[blockIdx.x] = buf[1023];
}
__global__ void k_scanB(int nb, int n)
{
    __shared__ int buf[128];
    const int tid = threadIdx.x;
    int v = (tid < nb) ? g_bsum[tid] : 0;
    buf[tid] = v;
    __syncthreads();
    for (int off = 1; off < 128; off <<= 1) {
        int t = (tid >= off) ? buf[tid - off] : 0;
        __syncthreads();
        buf[tid] += t;
        __syncthreads();
    }
    if (tid < nb) g_bsum[tid] = buf[tid] - v;   // exclusive block offsets
    if (tid == 127) g_eoff[n] = buf[127];       // total edges
}
__global__ void k_scanC(int n)
{
    int i = blockIdx.x * blockDim.x + threadIdx.x;
    if (i < n) g_eoff[i] = g_eoff[i] - g_cnt[i] + g_bsum[i >> 10];
}

// ---------------- counting-sort scatter --------------------------------------
__global__ void k_sort(const int* __restrict__ src, const int* __restrict__ dst,
                       const float* __restrict__ ea, int E)
{
    int e = blockIdx.x * blockDim.x + threadIdx.x;
    if (e < E) {
        int d = dst[e];
        int slot = g_eoff[d] + atomicAdd(&g_fill[d], 1);
        g_esrc[slot] = src[e];
        g_edst[slot] = d;
        g_eea[slot] = make_float2(ea[2 * e], ea[2 * e + 1]);
    }
}

// ---------------- input MLP (tf32 mma) + degree count ------------------------
__global__ void __launch_bounds__(NT, 2) k_input(
    const float* __restrict__ x,
    const float* __restrict__ W0, const float* __restrict__ b0,
    const float* __restrict__ W1, const float* __restrict__ b1,
    const int* __restrict__ dst, int E, int n, int ntiles)
{
    extern __shared__ float smem[];
    float* Wf  = smem;              // 16896
    float* As  = Wf + 16896;        // 64*132
    float* w0s = As + 8448;         // 256
    float* b0s = w0s + 256;         // 128
    float* xs  = b0s + 128;         // 128
    const int tid  = threadIdx.x;
    const int lane = tid & 31, w = tid >> 5;
    const int q = w & 3, h = w >> 2;
    const int g = lane >> 2, tg = lane & 3;

    for (int e = blockIdx.x * blockDim.x + tid; e < E; e += gridDim.x * blockDim.x)
        atomicAdd(&g_cnt[dst[e]], 1);

    stage_w_frag(Wf, W1, 16, tid);
    for (int t = tid; t < 256; t += NT) w0s[t] = W0[t];
    if (tid < 128) b0s[tid] = b0[tid];
    float bv[16];
    #pragma unroll
    for (int nt = 0; nt < 8; ++nt) {
        int col = h * 64 + 8 * nt + 2 * tg;
        bv[2 * nt]     = b1[col];
        bv[2 * nt + 1] = b1[col + 1];
    }
    const unsigned alane = a_lane_addr(As, 132, q, lane);

    for (int tile = blockIdx.x; tile < ntiles; tile += gridDim.x) {
        const int base = tile * 64;
        __syncthreads();
        if (tid < 128)
            xs[tid] = (base + (tid >> 1) < n) ? x[(size_t)base * 2 + tid] : 0.f;
        __syncthreads();

        for (int wi = tid; wi < 2048; wi += NT) {
            int row = wi >> 5, j = (wi & 31) << 2;
            float x0 = xs[row * 2], x1 = xs[row * 2 + 1];
            uint4 st;
            st.x = f2tf32(fmaxf(fmaf(x0, w0s[j+0], fmaf(x1, w0s[128+j+0], b0s[j+0])), 0.f));
            st.y = f2tf32(fmaxf(fmaf(x0, w0s[j+1], fmaf(x1, w0s[128+j+1], b0s[j+1])), 0.f));
            st.z = f2tf32(fmaxf(fmaf(x0, w0s[j+2], fmaf(x1, w0s[128+j+2], b0s[j+2])), 0.f));
            st.w = f2tf32(fmaxf(fmaf(x0, w0s[j+3], fmaf(x1, w0s[128+j+3], b0s[j+3])), 0.f));
            *(uint4*)(As + row * 132 + j) = st;
        }
        __syncthreads();

        float acc[8][4] = {};
        #pragma unroll
        for (int ks = 0; ks < 16; ++ks) {
            uint4 a = ldsm4(alane + (ks << 5));
            #pragma unroll
            for (int p = 0; p < 4; ++p) {
                uint4 b = *(const uint4*)(Wf + ((h * 16 + ks) * 4 + p) * 132 + lane * 4);
                mma8(acc[2 * p],     a, b.x, b.y);
                mma8(acc[2 * p + 1], a, b.z, b.w);
            }
        }

        int r0 = base + q * 16 + g;
        #pragma unroll
        for (int nt = 0; nt < 8; ++nt) {
            int col = h * 64 + 8 * nt + 2 * tg;
            if (r0 < n)
                *(float2*)(g_h + (size_t)r0 * HH + col) =
                    make_float2(fmaxf(acc[nt][0] + bv[2 * nt], 0.f),
                                fmaxf(acc[nt][1] + bv[2 * nt + 1], 0.f));
            if (r0 + 8 < n)
                *(float2*)(g_h + (size_t)(r0 + 8) * HH + col) =
                    make_float2(fmaxf(acc[nt][2] + bv[2 * nt], 0.f),
                                fmaxf(acc[nt][3] + bv[2 * nt + 1], 0.f));
        }
    }
}

// ---------------- P = BN?(h) @ W1a_top : bf16 mma, fused BN -------------------
__global__ void __launch_bounds__(NT, 3) k_precompute(
    const float* __restrict__ W,
    const float* __restrict__ gamma, const float* __restrict__ beta,
    int bnl, int n, int ntiles)
{
    extern __shared__ float smem[];
    unsigned* Wf = (unsigned*)smem;                      // 8448 words
    __nv_bfloat16* As = (__nv_bfloat16*)(Wf + 8448);     // 64 x 136 bf16
    float* scp = (float*)(As + 64 * 136);                // 144
    float* shp = scp + 144;                              // 144
    const int tid  = threadIdx.x;
    const int lane = tid & 31, w = tid >> 5;
    const int q = w & 3, h = w >> 2;
    const int g2 = lane >> 2, tg = lane & 3;

    stage_w_bf16(Wf, W, 8, tid);
    if (tid < 128) {
        int c = tid >> 3, s = tid & 7;
        if (bnl >= 0) {
            float invn = 1.f / (float)n;
            float mu  = g_sum[bnl * HH + tid] * invn;
            float var = g_sq[bnl * HH + tid] * invn - mu * mu;
            float sv = gamma[tid] * rsqrtf(var + EPSBN);
            scp[c * 9 + s] = sv; shp[c * 9 + s] = beta[tid] - mu * sv;
        } else { scp[c * 9 + s] = 1.f; shp[c * 9 + s] = 0.f; }
    }
    const unsigned alane = a_lane_addr_bf(As, 272, q, lane);
    const int pc = tid & 15;

    for (int tile = blockIdx.x; tile < ntiles; tile += gridDim.x) {
        const int base = tile * 64;
        __syncthreads();
        for (int wi = tid; wi < 1024; wi += NT) {
            int row = wi >> 4, j = pc * 8;
            int node = base + row;
            float v[8] = {0,0,0,0,0,0,0,0};
            if (node < n) {
                float4 va, vb;
                if (bnl >= 0) {
                    va = *(const float4*)(g_r + (size_t)node * HH + j);
                    vb = *(const float4*)(g_r + (size_t)node * HH + j + 4);
                    float vv[8] = {va.x,va.y,va.z,va.w,vb.x,vb.y,vb.z,vb.w};
                    #pragma unroll
                    for (int s = 0; s < 8; ++s)
                        v[s] = vv[s] * scp[pc * 9 + s] + shp[pc * 9 + s];
                    *(float4*)(g_h + (size_t)node * HH + j)     = make_float4(v[0],v[1],v[2],v[3]);
                    *(float4*)(g_h + (size_t)node * HH + j + 4) = make_float4(v[4],v[5],v[6],v[7]);
                } else {
                    va = *(const float4*)(g_h + (size_t)node * HH + j);
                    vb = *(const float4*)(g_h + (size_t)node * HH + j + 4);
                    v[0]=va.x; v[1]=va.y; v[2]=va.z; v[3]=va.w;
                    v[4]=vb.x; v[5]=vb.y; v[6]=vb.z; v[7]=vb.w;
                }
            }
            unsigned outw[4];
            #pragma unroll
            for (int s = 0; s < 4; ++s) {
                __nv_bfloat162 mb = __floats2bfloat162_rn(v[2*s], v[2*s+1]);
                outw[s] = *(unsigned*)&mb;
            }
            *(uint4*)(As + row * 136 + j) = *(uint4*)outw;
        }
        __syncthreads();

        float acc[8][4] = {};
        #pragma unroll
        for (int ks = 0; ks < 8; ++ks) {
            uint4 a = ldsm4(alane + ks * 32);
            #pragma unroll
            for (int pp = 0; pp < 4; ++pp) {
                uint4 b = *(const uint4*)(Wf + ((h * 8 + ks) * 4 + pp) * 132 + lane * 4);
                mma16(acc[2 * pp],     a, b.x, b.y);
                mma16(acc[2 * pp + 1], a, b.z, b.w);
            }
        }
        int r0 = base + q * 16 + g2;
        #pragma unroll
        for (int nt = 0; nt < 8; ++nt) {
            int col = h * 64 + 8 * nt + 2 * tg;
            if (r0 < n) {
                __nv_bfloat162 pv = __floats2bfloat162_rn(acc[nt][0], acc[nt][1]);
                g_pb[(size_t)r0 * 64 + (col >> 1)] = *(unsigned*)&pv;
            }
            if (r0 + 8 < n) {
                __nv_bfloat162 pv = __floats2bfloat162_rn(acc[nt][2], acc[nt][3]);
                g_pb[(size_t)(r0 + 8) * 64 + (col >> 1)] = *(unsigned*)&pv;
            }
        }
    }
}

// ---------------- edge kernel: prefetch + Ds overlay, 4 blocks/SM -------------
__global__ void __launch_bounds__(NT, 4) k_edge(
    const float* __restrict__ Wtail,
    const float* __restrict__ b1a,
    const float* __restrict__ W1b, const float* __restrict__ b1b,
    int E, int ntiles)
{
    extern __shared__ float smem[];
    unsigned* Wf = (unsigned*)smem;                      // 8448 words
    __nv_bfloat16* As = (__nv_bfloat16*)(Wf + 8448);     // 64 x 136 bf16 (4352 w)
    float* Ds  = (float*)As;                             // overlays As
    float* wt0p = (float*)(Wf + 8448 + 4352);            // 144
    float* wt1p = wt0p + 144;                            // 144
    float* bsp  = wt1p + 144;                            // 144
    float* b2s  = bsp + 144;                             // 128
    float* eas  = b2s + 128;                             // 128
    int*   sd   = (int*)(eas + 128);                     // 128

    const int tid  = threadIdx.x;
    const int lane = tid & 31, w = tid >> 5;
    const int q = w & 3, h = w >> 2;
    const int g2 = lane >> 2, tg = lane & 3;

    stage_w_bf16(Wf, W1b, 8, tid);
    if (tid < 128) {
        int c = tid >> 3, s = tid & 7;
        wt0p[c * 9 + s] = Wtail[tid];
        wt1p[c * 9 + s] = Wtail[128 + tid];
        bsp[c * 9 + s]  = b1a[tid];
        b2s[tid] = b1b[tid];
    }
    const unsigned alane = a_lane_addr_bf(As, 272, q, lane);
    const int pc = tid & 15;
    const int pairc = tid & 63, rg = tid >> 6;

    // prefetch first tile's metadata into registers
    int pe_src = 0, pe_dst = -1;
    float2 pe_ea = make_float2(0.f, 0.f);
    if (tid < 64) {
        int e = blockIdx.x * 64 + tid;
        if (e < E) { pe_src = g_esrc[e]; pe_dst = g_edst[e]; pe_ea = g_eea[e]; }
    }

    for (int tile = blockIdx.x; tile < ntiles; tile += gridDim.x) {
        __syncthreads();                 // Ds/sd/eas free from previous iter
        if (tid < 64) {
            sd[tid]      = pe_src;
            sd[64 + tid] = pe_dst;
            eas[2 * tid] = pe_ea.x; eas[2 * tid + 1] = pe_ea.y;
        }
        __syncthreads();
        // issue next tile's loads now; latency hidden by producer+mma+epilogue
        if (tid < 64) {
            int ntile = tile + gridDim.x;
            int e = ntile * 64 + tid;
            pe_src = 0; pe_dst = -1; pe_ea = make_float2(0.f, 0.f);
            if (ntile < ntiles && e < E) {
                pe_src = g_esrc[e]; pe_dst = g_edst[e]; pe_ea = g_eea[e];
            }
        }

        for (int wi = tid; wi < 1024; wi += NT) {
            int row = wi >> 4, j = pc * 8;
            uint4 p8 = ((const uint4*)(g_pb + (size_t)sd[row] * 64))[pc];
            float ev0 = eas[2 * row], ev1 = eas[2 * row + 1];
            unsigned pw[4] = {p8.x, p8.y, p8.z, p8.w};
            unsigned outw[4];
            #pragma unroll
            for (int s = 0; s < 4; ++s) {
                float2 pf = __bfloat1622float2(*(__nv_bfloat162*)&pw[s]);
                float m0 = fmaf(ev0, wt0p[pc*9 + 2*s],
                                fmaf(ev1, wt1p[pc*9 + 2*s],   pf.x + bsp[pc*9 + 2*s]));
                float m1 = fmaf(ev0, wt0p[pc*9 + 2*s+1],
                                fmaf(ev1, wt1p[pc*9 + 2*s+1], pf.y + bsp[pc*9 + 2*s+1]));
                __nv_bfloat162 mb = __floats2bfloat162_rn(fmaxf(m0, 0.f), fmaxf(m1, 0.f));
                outw[s] = *(unsigned*)&mb;
            }
            *(uint4*)(As + row * 136 + j) = *(uint4*)outw;
        }
        __syncthreads();

        float acc[8][4] = {};
        #pragma unroll
        for (int ks = 0; ks < 8; ++ks) {
            uint4 a = ldsm4(alane + ks * 32);
            #pragma unroll
            for (int pp = 0; pp < 4; ++pp) {
                uint4 b = *(const uint4*)(Wf + ((h * 8 + ks) * 4 + pp) * 132 + lane * 4);
                mma16(acc[2 * pp],     a, b.x, b.y);
                mma16(acc[2 * pp + 1], a, b.z, b.w);
            }
        }

        // two-phase epilogue: D staged into Ds (overlaid on As) -> segmented red
        #pragma unroll
        for (int p = 0; p < 2; ++p) {
            __syncthreads();
            if ((q >> 1) == p) {
                int lr = (q & 1) * 16 + g2;
                #pragma unroll
                for (int nt = 0; nt < 8; ++nt) {
                    int col = h * 64 + 8 * nt + 2 * tg;
                    float bb0 = b2s[col], bb1 = b2s[col + 1];
                    *(float2*)(Ds + lr * 132 + col) =
                        make_float2(fmaxf(acc[nt][0] + bb0, 0.f),
                                    fmaxf(acc[nt][1] + bb1, 0.f));
                    *(float2*)(Ds + (lr + 8) * 132 + col) =
                        make_float2(fmaxf(acc[nt][2] + bb0, 0.f),
                                    fmaxf(acc[nt][3] + bb1, 0.f));
                }
            }
            __syncthreads();
            int gr = p * 32 + rg * 8;
            float2 sv = make_float2(0.f, 0.f);
            int cur = sd[64 + gr];
            #pragma unroll
            for (int r = 0; r < 8; ++r) {
                int dd = sd[64 + gr + r];
                float2 v = *(const float2*)(Ds + (rg * 8 + r) * 132 + pairc * 2);
                if (dd != cur) {
                    if (cur >= 0)
                        asm volatile("red.global.add.v2.f32 [%0], {%1,%2};"
                                     :: "l"(g_agg + (size_t)cur * HH + pairc * 2),
                                        "f"(sv.x), "f"(sv.y) : "memory");
                    sv = make_float2(0.f, 0.f);
                    cur = dd;
                }
                sv.x += v.x; sv.y += v.y;
            }
            if (cur >= 0)
                asm volatile("red.global.add.v2.f32 [%0], {%1,%2};"
                             :: "l"(g_agg + (size_t)cur * HH + pairc * 2),
                                "f"(sv.x), "f"(sv.y) : "memory");
        }
    }
}

// ---------------- update1: U = relu([h | agg/deg] @ W2a + b2a) -> g_ub -------
__global__ void __launch_bounds__(NT, 2) k_update1(
    const float* __restrict__ W2a, const float* __restrict__ b2a,
    int n, int ntiles, int zero_agg)
{
    extern __shared__ float smem[];
    unsigned* Wf = (unsigned*)smem;                      // 16896 words
    __nv_bfloat16* As = (__nv_bfloat16*)(Wf + 16896);    // 64 x 264 bf16
    float* sinv = (float*)(As + 64 * 264);               // 64
    const int tid  = threadIdx.x;
    const int lane = tid & 31, w = tid >> 5;
    const int q = w & 3, h = w >> 2;
    const int g = lane >> 2, tg = lane & 3;

    stage_w_bf16(Wf, W2a, 16, tid);
    float bv[16];
    #pragma unroll
    for (int nt = 0; nt < 8; ++nt) {
        int col = h * 64 + 8 * nt + 2 * tg;
        bv[2 * nt]     = b2a[col];
        bv[2 * nt + 1] = b2a[col + 1];
    }
    const unsigned alane = a_lane_addr_bf(As, 528, q, lane);
    const int cu = tid & 31;

    for (int tile = blockIdx.x; tile < ntiles; tile += gridDim.x) {
        const int base = tile * 64;
        __syncthreads();
        if (tid < 64) {
            int node = base + tid;
            sinv[tid] = (node < n) ? 1.f / fmaxf((float)g_cnt[node], 1.f) : 0.f;
        }
        __syncthreads();

        for (int wi = tid; wi < 2048; wi += NT) {
            int row = wi >> 5, j = cu * 8;
            int node = base + row;
            float v[8] = {0,0,0,0,0,0,0,0};
            if (node < n) {
                if (cu < 16) {
                    float4 va = *(const float4*)(g_h + (size_t)node * HH + j);
                    float4 vb = *(const float4*)(g_h + (size_t)node * HH + j + 4);
                    v[0]=va.x; v[1]=va.y; v[2]=va.z; v[3]=va.w;
                    v[4]=vb.x; v[5]=vb.y; v[6]=vb.z; v[7]=vb.w;
                } else {
                    int ja = j - 128;
                    float4 va = *(const float4*)(g_agg + (size_t)node * HH + ja);
                    float4 vb = *(const float4*)(g_agg + (size_t)node * HH + ja + 4);
                    float iv = sinv[row];
                    v[0]=va.x*iv; v[1]=va.y*iv; v[2]=va.z*iv; v[3]=va.w*iv;
                    v[4]=vb.x*iv; v[5]=vb.y*iv; v[6]=vb.z*iv; v[7]=vb.w*iv;
                    if (zero_agg) {
                        *(float4*)(g_agg + (size_t)node * HH + ja)     = make_float4(0,0,0,0);
                        *(float4*)(g_agg + (size_t)node * HH + ja + 4) = make_float4(0,0,0,0);
                    }
                }
            }
            unsigned outw[4];
            #pragma unroll
            for (int s = 0; s < 4; ++s) {
                __nv_bfloat162 mb = __floats2bfloat162_rn(v[2*s], v[2*s+1]);
                outw[s] = *(unsigned*)&mb;
            }
            *(uint4*)(As + row * 264 + j) = *(uint4*)outw;
        }
        __syncthreads();

        float acc[8][4] = {};
        #pragma unroll
        for (int ks = 0; ks < 16; ++ks) {
            uint4 a = ldsm4(alane + ks * 32);
            #pragma unroll
            for (int pp = 0; pp < 4; ++pp) {
                uint4 b = *(const uint4*)(Wf + ((h * 16 + ks) * 4 + pp) * 132 + lane * 4);
                mma16(acc[2 * pp],     a, b.x, b.y);
                mma16(acc[2 * pp + 1], a, b.z, b.w);
            }
        }

        int r0 = base + q * 16 + g;
        #pragma unroll
        for (int nt = 0; nt < 8; ++nt) {
            int col = h * 64 + 8 * nt + 2 * tg;
            if (r0 < n) {
                __nv_bfloat162 uv = __floats2bfloat162_rn(
                    fmaxf(acc[nt][0] + bv[2 * nt], 0.f),
                    fmaxf(acc[nt][1] + bv[2 * nt + 1], 0.f));
                g_ub[(size_t)r0 * 64 + (col >> 1)] = *(unsigned*)&uv;
            }
            if (r0 + 8 < n) {
                __nv_bfloat162 uv = __floats2bfloat162_rn(
                    fmaxf(acc[nt][2] + bv[2 * nt], 0.f),
                    fmaxf(acc[nt][3] + bv[2 * nt + 1], 0.f));
                g_ub[(size_t)(r0 + 8) * 64 + (col >> 1)] = *(unsigned*)&uv;
            }
        }
    }
}

// ---------------- update2: out=sigmoid(U@W2b+b), r=h+out, BN stats (bf16) ----
__global__ void __launch_bounds__(NT, 3) k_update2(
    const float* __restrict__ W2b, const float* __restrict__ b2b,
    int l, int n, int ntiles)
{
    extern __shared__ float smem[];
    unsigned* Wf = (unsigned*)smem;                      // 8448 words
    __nv_bfloat16* As = (__nv_bfloat16*)(Wf + 8448);     // union with Dr
    float* Dr = (float*)(Wf + 8448);
    const int tid  = threadIdx.x;
    const int lane = tid & 31, w = tid >> 5;
    const int q = w & 3, h = w >> 2;
    const int g = lane >> 2, tg = lane & 3;

    stage_w_bf16(Wf, W2b, 8, tid);
    float bv[16];
    #pragma unroll
    for (int nt = 0; nt < 8; ++nt) {
        int col = h * 64 + 8 * nt + 2 * tg;
        bv[2 * nt]     = b2b[col];
        bv[2 * nt + 1] = b2b[col + 1];
    }
    const unsigned alane = a_lane_addr_bf(As, 272, q, lane);
    const int pc = tid & 15;

    for (int tile = blockIdx.x; tile < ntiles; tile += gridDim.x) {
        const int base = tile * 64;
        __syncthreads();
        for (int wi = tid; wi < 1024; wi += NT) {
            int row = wi >> 4;
            int node = base + row;
            uint4 u = make_uint4(0, 0, 0, 0);
            if (node < n) u = ((const uint4*)(g_ub + (size_t)node * 64))[pc];
            *(uint4*)(As + row * 136 + pc * 8) = u;
        }
        __syncthreads();

        float acc[8][4] = {};
        #pragma unroll
        for (int ks = 0; ks < 8; ++ks) {
            uint4 a = ldsm4(alane + ks * 32);
            #pragma unroll
            for (int pp = 0; pp < 4; ++pp) {
                uint4 b = *(const uint4*)(Wf + ((h * 8 + ks) * 4 + pp) * 132 + lane * 4);
                mma16(acc[2 * pp],     a, b.x, b.y);
                mma16(acc[2 * pp + 1], a, b.z, b.w);
            }
        }
        __syncthreads();

        int r0 = base + q * 16 + g;
        #pragma unroll
        for (int nt = 0; nt < 8; ++nt) {
            int col = h * 64 + 8 * nt + 2 * tg;
            float2 rv0 = make_float2(0.f, 0.f), rv1 = make_float2(0.f, 0.f);
            if (r0 < n) {
                float2 hv = *(const float2*)(g_h + (size_t)r0 * HH + col);
                rv0.x = hv.x + 1.f / (1.f + expf(-(acc[nt][0] + bv[2 * nt])));
                rv0.y = hv.y + 1.f / (1.f + expf(-(acc[nt][1] + bv[2 * nt + 1])));
            }
            if (r0 + 8 < n) {
                float2 hv = *(const float2*)(g_h + (size_t)(r0 + 8) * HH + col);
                rv1.x = hv.x + 1.f / (1.f + expf(-(acc[nt][2] + bv[2 * nt])));
                rv1.y = hv.y + 1.f / (1.f + expf(-(acc[nt][3] + bv[2 * nt + 1])));
            }
            *(float2*)(Dr + (q * 16 + g) * 132 + col)     = rv0;
            *(float2*)(Dr + (q * 16 + g + 8) * 132 + col) = rv1;
        }
        __syncthreads();

        for (int wi = tid; wi < 2048; wi += NT) {
            int row = wi >> 5, j = (wi & 31) << 2;
            if (base + row < n) {
                float4 v = *(const float4*)(Dr + row * 132 + j);
                *(float4*)(g_r + (size_t)(base + row) * HH + j) = v;
            }
        }
        {
            int c = tid & 127, half = tid >> 7;
            float s = 0.f, s2 = 0.f;
            #pragma unroll 8
            for (int r = half * 32; r < half * 32 + 32; ++r) {
                float v = Dr[r * 132 + c];
                s += v; s2 += v * v;
            }
            atomicAdd(&g_sum[l * HH + c], s);
            atomicAdd(&g_sq[l * HH + c],  s2);
        }
    }
}

// ---------------- final MLP (tf32 mma) with fused BN --------------------------
__global__ void __launch_bounds__(NT, 2) k_final(
    const float* __restrict__ Wfp, const float* __restrict__ bf,
    const float* __restrict__ Wo, const float* __restrict__ bo,
    const float* __restrict__ gamma, const float* __restrict__ beta,
    int bnl, float* __restrict__ out, int n, int ntiles)
{
    extern __shared__ float smem[];
    float* Wf = smem;               // 16896
    float* As = Wf + 16896;         // 64*132
    float* sc = As + 8448;          // 128
    float* sh = sc + 128;           // 128
    const int tid  = threadIdx.x;
    const int lane = tid & 31, w = tid >> 5;
    const int q = w & 3, h = w >> 2;
    const int g = lane >> 2, tg = lane & 3;

    stage_w_frag(Wf, Wfp, 16, tid);
    if (tid < 128) {
        float invn = 1.f / (float)n;
        float mu  = g_sum[bnl * HH + tid] * invn;
        float var = g_sq[bnl * HH + tid] * invn - mu * mu;
        float s = gamma[tid] * rsqrtf(var + EPSBN);
        sc[tid] = s; sh[tid] = beta[tid] - mu * s;
    }
    float bv[16];
    #pragma unroll
    for (int nt = 0; nt < 8; ++nt) {
        int col = h * 64 + 8 * nt + 2 * tg;
        bv[2 * nt]     = bf[col];
        bv[2 * nt + 1] = bf[col + 1];
    }
    const unsigned alane = a_lane_addr(As, 132, q, lane);

    for (int tile = blockIdx.x; tile < ntiles; tile += gridDim.x) {
        const int base = tile * 64;
        __syncthreads();
        for (int wi = tid; wi < 2048; wi += NT) {
            int row = wi >> 5, j = (wi & 31) << 2;
            float4 v = make_float4(0.f, 0.f, 0.f, 0.f);
            if (base + row < n) {
                v = *(const float4*)(g_r + (size_t)(base + row) * HH + j);
                v.x = v.x * sc[j + 0] + sh[j + 0];
                v.y = v.y * sc[j + 1] + sh[j + 1];
                v.z = v.z * sc[j + 2] + sh[j + 2];
                v.w = v.w * sc[j + 3] + sh[j + 3];
            }
            uint4 st = make_uint4(f2tf32(v.x), f2tf32(v.y), f2tf32(v.z), f2tf32(v.w));
            *(uint4*)(As + row * 132 + j) = st;
        }
        __syncthreads();

        float acc[8][4] = {};
        #pragma unroll
        for (int ks = 0; ks < 16; ++ks) {
            uint4 a = ldsm4(alane + (ks << 5));
            #pragma unroll
            for (int p = 0; p < 4; ++p) {
                uint4 b = *(const uint4*)(Wf + ((h * 16 + ks) * 4 + p) * 132 + lane * 4);
                mma8(acc[2 * p],     a, b.x, b.y);
                mma8(acc[2 * p + 1], a, b.z, b.w);
            }
        }
        __syncthreads();   // ldsm done -> reuse As as f tile

        #pragma unroll
        for (int nt = 0; nt < 8; ++nt) {
            int col = h * 64 + 8 * nt + 2 * tg;
            *(float2*)(As + (q * 16 + g) * 132 + col) =
                make_float2(fmaxf(acc[nt][0] + bv[2 * nt], 0.f),
                            fmaxf(acc[nt][1] + bv[2 * nt + 1], 0.f));
            *(float2*)(As + (q * 16 + g + 8) * 132 + col) =
                make_float2(fmaxf(acc[nt][2] + bv[2 * nt], 0.f),
                            fmaxf(acc[nt][3] + bv[2 * nt + 1], 0.f));
        }
        __syncthreads();

        const int rw = tid >> 5;
        #pragma unroll
        for (int rr = 0; rr < 8; ++rr) {
            int row = rw * 8 + rr;
            float sAcc = 0.f;
            #pragma unroll
            for (int qq = 0; qq < 4; ++qq)
                sAcc += As[row * 132 + lane + 32 * qq] * Wo[lane + 32 * qq];
            #pragma unroll
            for (int off = 16; off; off >>= 1)
                sAcc += __shfl_xor_sync(0xffffffffu, sAcc, off);
            if (lane == 0 && base + row < n)
                out[base + row] = 1.f / (1.f + expf(-(sAcc + bo[0])));
        }
    }
}

// ---------------- launcher -----------------------------------------------------
extern "C" void kernel_launch(void* const* d_in, const int* in_sizes, int n_in,
                              void* d_out, int out_size)
{
    const float* x    = (const float*)d_in[0];
    const float* ea   = (const float*)d_in[1];
    const int*   ei   = (const int*)  d_in[2];
    const float* W0   = (const float*)d_in[4];
    const float* b0   = (const float*)d_in[5];
    const float* W1   = (const float*)d_in[6];
    const float* b1   = (const float*)d_in[7];
    const float* W1a  = (const float*)d_in[8];
    const float* b1a  = (const float*)d_in[9];
    const float* W1b  = (const float*)d_in[10];
    const float* b1b  = (const float*)d_in[11];
    const float* W2a  = (const float*)d_in[12];
    const float* b2a  = (const float*)d_in[13];
    const float* W2b  = (const float*)d_in[14];
    const float* b2b  = (const float*)d_in[15];
    const float* gam  = (const float*)d_in[16];
    const float* bet  = (const float*)d_in[17];
    const float* Wf   = (const float*)d_in[18];
    const float* bf   = (const float*)d_in[19];
    const float* Wo   = (const float*)d_in[20];
    const float* bo   = (const float*)d_in[21];
    float* out = (float*)d_out;

    const int n = in_sizes[0] / 2;
    const int E = in_sizes[2] / 2;
    const int* srcp = ei;
    const int* dstp = ei + E;

    const int ntiles_n = (n + 63) / 64;
    const int ntiles_e = (E + 63) / 64;
    const int nscan    = (n + 1023) / 1024;
    const int gPers2   = 296;
    const int gPers3   = 444;
    const int gPers4   = 592;

    const size_t SM_IN = (size_t)(16896 + 8448 + 256 + 128 + 128) * 4;      // 103424
    const size_t SM_P  = (size_t)(8448 + 4352 + 288) * 4;                   // 52352
    const size_t SM_E  = (size_t)(8448 + 4352 + 432 + 128 + 128 + 128) * 4; // 54464
    const size_t SM_U1 = (size_t)(16896 + 8448 + 64) * 4;                   // 101632
    const size_t SM_U2 = (size_t)(8448 + 8448) * 4;                         // 67584
    const size_t SM_F  = (size_t)(16896 + 8448 + 256) * 4;                  // 102400

    cudaFuncSetAttribute(k_input, cudaFuncAttributeMaxDynamicSharedMemorySize, (int)SM_IN);
    cudaFuncSetAttribute(k_edge, cudaFuncAttributeMaxDynamicSharedMemorySize, (int)SM_E);
    cudaFuncSetAttribute(k_precompute, cudaFuncAttributeMaxDynamicSharedMemorySize, (int)SM_P);
    cudaFuncSetAttribute(k_update1, cudaFuncAttributeMaxDynamicSharedMemorySize, (int)SM_U1);
    cudaFuncSetAttribute(k_update2, cudaFuncAttributeMaxDynamicSharedMemorySize, (int)SM_U2);
    cudaFuncSetAttribute(k_final, cudaFuncAttributeMaxDynamicSharedMemorySize, (int)SM_F);

    k_zero<<<1024, 256>>>(n);
    k_input<<<gPers2, NT, SM_IN>>>(x, W0, b0, W1, b1, dstp, E, n, ntiles_n);
    k_scanA<<<nscan, 1024>>>(n);
    k_scanB<<<1, 128>>>(nscan, n);
    k_scanC<<<(n + 255) / 256, 256>>>(n);
    k_sort<<<(E + 255) / 256, 256>>>(srcp, dstp, ea, E);

    for (int l = 0; l < LL; ++l) {
        const float* W1a_l  = W1a + (size_t)l * 130 * 128;
        const float* W1a_t  = W1a_l + 128 * 128;
        const float* b1a_l  = b1a + (size_t)l * 128;
        const float* W1b_l  = W1b + (size_t)l * 128 * 128;
        const float* b1b_l  = b1b + (size_t)l * 128;
        const float* W2a_l  = W2a + (size_t)l * 256 * 128;
        const float* b2a_l  = b2a + (size_t)l * 128;
        const float* W2b_l  = W2b + (size_t)l * 128 * 128;
        const float* b2b_l  = b2b + (size_t)l * 128;
        const float* gam_p  = (l > 0) ? gam + (size_t)(l - 1) * 128 : gam;
        const float* bet_p  = (l > 0) ? bet + (size_t)(l - 1) * 128 : bet;

        k_precompute<<<gPers3, NT, SM_P>>>(W1a_l, gam_p, bet_p, l - 1, n, ntiles_n);
        k_edge<<<gPers4, NT, SM_E>>>(W1a_t, b1a_l, W1b_l, b1b_l, E, ntiles_e);
        k_update1<<<gPers2, NT, SM_U1>>>(W2a_l, b2a_l, n, ntiles_n,
                                         (l < LL - 1) ? 1 : 0);
        k_update2<<<gPers3, NT, SM_U2>>>(W2b_l, b2b_l, l, n, ntiles_n);
    }

    k_final<<<gPers2, NT, SM_F>>>(Wf, bf, Wo, bo,
                                  gam + (size_t)(LL - 1) * 128,
                                  bet + (size_t)(LL - 1) * 128,
                                  LL - 1, out, n, ntiles_n);
}